// round 4
// baseline (speedup 1.0000x reference)
#include <cuda_runtime.h>

// Problem constants
#define Bb 16
#define Nn 577
#define Cc 768
#define Hh 12
#define Dd 64
#define SCALEF 0.125f
#define ALPHAF 0.1f
#define MM (Bb * Nn)        // 9232 rows
#define QKVN (3 * Cc)       // 2304
#define KDIM 768

// Scratch (static device globals — no allocation allowed in kernel_launch)
__device__ float g_q[Bb * Hh * Nn * Dd];
__device__ float g_k[Bb * Hh * Nn * Dd];
__device__ float g_v[Bb * Hh * Nn * Dd];
__device__ float g_ao[Bb * Nn * Cc];

// ---------------------------------------------------------------------------
// QKV GEMM: y = x @ w_qkv + b_qkv, scattered into q/k/v [B,H,N,D] layout.
// Classic 128x128x8 register-tiled SGEMM, 256 threads, 8x8 per thread.
// ---------------------------------------------------------------------------
__global__ __launch_bounds__(256) void sgemm_qkv(
    const float* __restrict__ A,   // x      [MM, 768]
    const float* __restrict__ Bm,  // w_qkv  [768, 2304]
    const float* __restrict__ bias)
{
    __shared__ float As[8][128];
    __shared__ float Bs[8][128];
    const int tid = threadIdx.x;
    const int rowBase = blockIdx.y * 128;
    const int colBase = blockIdx.x * 128;
    const int tx = tid & 15, ty = tid >> 4;

    float acc[8][8];
#pragma unroll
    for (int i = 0; i < 8; i++)
#pragma unroll
        for (int j = 0; j < 8; j++) acc[i][j] = 0.f;

    const int arow = tid >> 1, aseg = (tid & 1) * 4;
    const int brow = tid >> 5, bcol = (tid & 31) * 4;

    for (int k0 = 0; k0 < KDIM; k0 += 8) {
        float4 a4 = make_float4(0.f, 0.f, 0.f, 0.f);
        int gr = rowBase + arow;
        if (gr < MM) a4 = *(const float4*)(A + (long)gr * KDIM + k0 + aseg);
        As[aseg + 0][arow] = a4.x;
        As[aseg + 1][arow] = a4.y;
        As[aseg + 2][arow] = a4.z;
        As[aseg + 3][arow] = a4.w;

        float4 b4 = *(const float4*)(Bm + (long)(k0 + brow) * QKVN + colBase + bcol);
        *(float4*)&Bs[brow][bcol] = b4;
        __syncthreads();

#pragma unroll
        for (int kk = 0; kk < 8; kk++) {
            float4 a0 = *(float4*)&As[kk][ty * 8];
            float4 a1 = *(float4*)&As[kk][ty * 8 + 4];
            float4 b0 = *(float4*)&Bs[kk][tx * 8];
            float4 b1 = *(float4*)&Bs[kk][tx * 8 + 4];
            float af[8] = {a0.x, a0.y, a0.z, a0.w, a1.x, a1.y, a1.z, a1.w};
            float bf[8] = {b0.x, b0.y, b0.z, b0.w, b1.x, b1.y, b1.z, b1.w};
#pragma unroll
            for (int i = 0; i < 8; i++)
#pragma unroll
                for (int j = 0; j < 8; j++) acc[i][j] = fmaf(af[i], bf[j], acc[i][j]);
        }
        __syncthreads();
    }

#pragma unroll
    for (int i = 0; i < 8; i++) {
        int gr = rowBase + ty * 8 + i;
        if (gr >= MM) continue;
        int bidx = gr / Nn, n = gr % Nn;
#pragma unroll
        for (int j = 0; j < 8; j++) {
            int col = colBase + tx * 8 + j;
            float val = acc[i][j] + bias[col];
            int which = col / Cc;          // 0=q 1=k 2=v (constant per 128-tile)
            int c = col % Cc;
            int h = c >> 6, d = c & 63;
            float* dst = (which == 0) ? g_q : ((which == 1) ? g_k : g_v);
            dst[(((long)bidx * Hh + h) * Nn + n) * Dd + d] = val;
        }
    }
}

// ---------------------------------------------------------------------------
// Attention: one block per (b,h,row). Scores in smem, full softmax, then P@V.
// Row 0 additionally emits pre-reweight patch_attn and applies the CLS reweight.
// ---------------------------------------------------------------------------
__global__ __launch_bounds__(128) void attn_kernel(
    const float* __restrict__ aw,   // attn_weight [B, N-1]
    float* __restrict__ patch)      // [B*H, N-1]
{
    const int bh = blockIdx.y;
    const int b = bh / Hh;
    const int n = blockIdx.x;
    const int tid = threadIdx.x;

    __shared__ float qs[64];
    __shared__ float sc[Nn];
    __shared__ float red[4];
    __shared__ float osh[128];

    const float* qrow = g_q + ((long)bh * Nn + n) * Dd;
    if (tid < 64) qs[tid] = qrow[tid];
    __syncthreads();

    for (int m = tid; m < Nn; m += 128) {
        const float4* kp = (const float4*)(g_k + ((long)bh * Nn + m) * Dd);
        float acc = 0.f;
#pragma unroll
        for (int i = 0; i < 16; i++) {
            float4 k4 = kp[i];
            acc = fmaf(qs[4 * i + 0], k4.x, acc);
            acc = fmaf(qs[4 * i + 1], k4.y, acc);
            acc = fmaf(qs[4 * i + 2], k4.z, acc);
            acc = fmaf(qs[4 * i + 3], k4.w, acc);
        }
        float s = acc * SCALEF;
        if (n == 0 && m > 0) {
            patch[(long)bh * (Nn - 1) + m - 1] = s;   // pre-reweight score
            s *= (aw[(long)b * (Nn - 1) + m - 1] * ALPHAF + (1.0f - ALPHAF));
        }
        sc[m] = s;
    }
    __syncthreads();

    // block max
    float lm = -1e30f;
    for (int m = tid; m < Nn; m += 128) lm = fmaxf(lm, sc[m]);
#pragma unroll
    for (int o = 16; o; o >>= 1) lm = fmaxf(lm, __shfl_xor_sync(0xffffffffu, lm, o));
    if ((tid & 31) == 0) red[tid >> 5] = lm;
    __syncthreads();
    const float gmax = fmaxf(fmaxf(red[0], red[1]), fmaxf(red[2], red[3]));

    // exp + sum
    float ls = 0.f;
    for (int m = tid; m < Nn; m += 128) {
        float e = __expf(sc[m] - gmax);
        sc[m] = e;
        ls += e;
    }
#pragma unroll
    for (int o = 16; o; o >>= 1) ls += __shfl_xor_sync(0xffffffffu, ls, o);
    __syncthreads();                  // sc writes + red(max) reads complete
    if ((tid & 31) == 0) red[tid >> 5] = ls;
    __syncthreads();
    const float inv = 1.0f / (red[0] + red[1] + red[2] + red[3]);

    // out[d] = sum_m p[m] * V[m][d]
    const int d = tid & 63, half = tid >> 6;
    float acc = 0.f;
    for (int m = half; m < Nn; m += 2)
        acc = fmaf(sc[m], g_v[((long)bh * Nn + m) * Dd + d], acc);
    osh[tid] = acc;
    __syncthreads();
    if (tid < 64) {
        int h = bh % Hh;
        g_ao[((long)(b * Nn + n)) * Cc + h * Dd + tid] = (osh[tid] + osh[tid + 64]) * inv;
    }
}

// ---------------------------------------------------------------------------
// Proj GEMM: out = g_ao @ w_proj + b_proj  -> d_out[0 : MM*768]
// ---------------------------------------------------------------------------
__global__ __launch_bounds__(256) void sgemm_proj(
    const float* __restrict__ Bm,   // w_proj [768, 768]
    const float* __restrict__ bias,
    float* __restrict__ out)
{
    __shared__ float As[8][128];
    __shared__ float Bs[8][128];
    const int tid = threadIdx.x;
    const int rowBase = blockIdx.y * 128;
    const int colBase = blockIdx.x * 128;
    const int tx = tid & 15, ty = tid >> 4;

    float acc[8][8];
#pragma unroll
    for (int i = 0; i < 8; i++)
#pragma unroll
        for (int j = 0; j < 8; j++) acc[i][j] = 0.f;

    const int arow = tid >> 1, aseg = (tid & 1) * 4;
    const int brow = tid >> 5, bcol = (tid & 31) * 4;

    for (int k0 = 0; k0 < KDIM; k0 += 8) {
        float4 a4 = make_float4(0.f, 0.f, 0.f, 0.f);
        int gr = rowBase + arow;
        if (gr < MM) a4 = *(const float4*)(g_ao + (long)gr * KDIM + k0 + aseg);
        As[aseg + 0][arow] = a4.x;
        As[aseg + 1][arow] = a4.y;
        As[aseg + 2][arow] = a4.z;
        As[aseg + 3][arow] = a4.w;

        float4 b4 = *(const float4*)(Bm + (long)(k0 + brow) * Cc + colBase + bcol);
        *(float4*)&Bs[brow][bcol] = b4;
        __syncthreads();

#pragma unroll
        for (int kk = 0; kk < 8; kk++) {
            float4 a0 = *(float4*)&As[kk][ty * 8];
            float4 a1 = *(float4*)&As[kk][ty * 8 + 4];
            float4 b0 = *(float4*)&Bs[kk][tx * 8];
            float4 b1 = *(float4*)&Bs[kk][tx * 8 + 4];
            float af[8] = {a0.x, a0.y, a0.z, a0.w, a1.x, a1.y, a1.z, a1.w};
            float bf[8] = {b0.x, b0.y, b0.z, b0.w, b1.x, b1.y, b1.z, b1.w};
#pragma unroll
            for (int i = 0; i < 8; i++)
#pragma unroll
                for (int j = 0; j < 8; j++) acc[i][j] = fmaf(af[i], bf[j], acc[i][j]);
        }
        __syncthreads();
    }

#pragma unroll
    for (int i = 0; i < 8; i++) {
        int gr = rowBase + ty * 8 + i;
        if (gr >= MM) continue;
#pragma unroll
        for (int j = 0; j < 8; j++) {
            int col = colBase + tx * 8 + j;
            out[(long)gr * Cc + col] = acc[i][j] + bias[col];
        }
    }
}

// ---------------------------------------------------------------------------
extern "C" void kernel_launch(void* const* d_in, const int* in_sizes, int n_in,
                              void* d_out, int out_size)
{
    const float* x      = (const float*)d_in[0];
    const float* aw     = (const float*)d_in[1];
    const float* w_qkv  = (const float*)d_in[2];
    const float* b_qkv  = (const float*)d_in[3];
    const float* w_proj = (const float*)d_in[4];
    const float* b_proj = (const float*)d_in[5];

    float* out   = (float*)d_out;
    float* patch = out + (long)Bb * Nn * Cc;   // patch_attn after main output

    dim3 gq(QKVN / 128, (MM + 127) / 128);     // 18 x 73
    sgemm_qkv<<<gq, 256>>>(x, w_qkv, b_qkv);

    dim3 ga(Nn, Bb * Hh);                      // 577 x 192
    attn_kernel<<<ga, 128>>>(aw, patch);

    dim3 gp(Cc / 128, (MM + 127) / 128);       // 6 x 73
    sgemm_proj<<<gp, 256>>>(w_proj, b_proj, out);
}

// round 6
// speedup vs baseline: 1.9459x; 1.9459x over previous
#include <cuda_runtime.h>

// Problem constants
#define Bb 16
#define Nn 577
#define Cc 768
#define Hh 12
#define Dd 64
#define SCALEF 0.125f
#define ALPHAF 0.1f
#define MM (Bb * Nn)        // 9232 rows
#define QKVN (3 * Cc)       // 2304
#define KDIM 768
#define NPATCH (Nn - 1)     // 576
#define NPAD 580            // Nn padded to multiple of 4 (16B-aligned rows)

// Scratch (static device globals — no allocation allowed in kernel_launch)
// Q and K stored d-major with padded pitch: [bh][d][NPAD]
__device__ float g_qT[Bb * Hh * Dd * NPAD];
__device__ float g_kT[Bb * Hh * Dd * NPAD];
__device__ float g_v [Bb * Hh * Nn * Dd];   // [bh][n][d]
__device__ float g_ao[Bb * Nn * Cc];

// ---------------------------------------------------------------------------
// QKV GEMM: y = x @ w_qkv + b_qkv, scattered into qT/kT (d-major) and v.
// ---------------------------------------------------------------------------
__global__ __launch_bounds__(256) void sgemm_qkv(
    const float* __restrict__ A,   // x      [MM, 768]
    const float* __restrict__ Bm,  // w_qkv  [768, 2304]
    const float* __restrict__ bias)
{
    __shared__ float As[8][128];
    __shared__ float Bs[8][128];
    const int tid = threadIdx.x;
    const int rowBase = blockIdx.y * 128;
    const int colBase = blockIdx.x * 128;
    const int tx = tid & 15, ty = tid >> 4;

    float acc[8][8];
#pragma unroll
    for (int i = 0; i < 8; i++)
#pragma unroll
        for (int j = 0; j < 8; j++) acc[i][j] = 0.f;

    const int arow = tid >> 1, aseg = (tid & 1) * 4;
    const int brow = tid >> 5, bcol = (tid & 31) * 4;

    for (int k0 = 0; k0 < KDIM; k0 += 8) {
        float4 a4 = make_float4(0.f, 0.f, 0.f, 0.f);
        int gr = rowBase + arow;
        if (gr < MM) a4 = *(const float4*)(A + (long)gr * KDIM + k0 + aseg);
        As[aseg + 0][arow] = a4.x;
        As[aseg + 1][arow] = a4.y;
        As[aseg + 2][arow] = a4.z;
        As[aseg + 3][arow] = a4.w;

        float4 b4 = *(const float4*)(Bm + (long)(k0 + brow) * QKVN + colBase + bcol);
        *(float4*)&Bs[brow][bcol] = b4;
        __syncthreads();

#pragma unroll
        for (int kk = 0; kk < 8; kk++) {
            float4 a0 = *(float4*)&As[kk][ty * 8];
            float4 a1 = *(float4*)&As[kk][ty * 8 + 4];
            float4 b0 = *(float4*)&Bs[kk][tx * 8];
            float4 b1 = *(float4*)&Bs[kk][tx * 8 + 4];
            float af[8] = {a0.x, a0.y, a0.z, a0.w, a1.x, a1.y, a1.z, a1.w};
            float bf[8] = {b0.x, b0.y, b0.z, b0.w, b1.x, b1.y, b1.z, b1.w};
#pragma unroll
            for (int i = 0; i < 8; i++)
#pragma unroll
                for (int j = 0; j < 8; j++) acc[i][j] = fmaf(af[i], bf[j], acc[i][j]);
        }
        __syncthreads();
    }

#pragma unroll
    for (int i = 0; i < 8; i++) {
        int gr = rowBase + ty * 8 + i;
        if (gr >= MM) continue;
        int bidx = gr / Nn, n = gr % Nn;
#pragma unroll
        for (int j = 0; j < 8; j++) {
            int col = colBase + tx * 8 + j;
            float val = acc[i][j] + bias[col];
            int which = col / Cc;          // 0=q 1=k 2=v (constant per 128-tile)
            int c = col % Cc;
            int h = c >> 6, d = c & 63;
            long bh = (long)bidx * Hh + h;
            if (which == 0)      g_qT[(bh * Dd + d) * NPAD + n] = val;
            else if (which == 1) g_kT[(bh * Dd + d) * NPAD + n] = val;
            else                 g_v [(bh * Nn + n) * Dd + d] = val;
        }
    }
}

// ---------------------------------------------------------------------------
// Flash-style attention: block = 64 q-rows of one (b,h); 256 threads.
// Iterate keys in chunks of 64 with online softmax.
// Thread (tx,ty) owns a 4x4 tile: rows 4ty..4ty+3, cols 4tx..4tx+3 in both
// the S=QK^T gemm and the O=PV gemm (same rows -> softmax state in regs).
// ---------------------------------------------------------------------------
#define QT 64
#define KT 64
#define NQT ((Nn + QT - 1) / QT)   // 10
#define NKT ((Nn + KT - 1) / KT)   // 10
#define PSP 68                     // Ps pitch (floats): 16B-aligned, bank-spread

__global__ __launch_bounds__(256) void attn_flash(
    const float* __restrict__ aw,   // attn_weight [B, 576]
    float* __restrict__ patch)      // [B*H, 576]
{
    extern __shared__ float sm[];
    float* Qs = sm;                  // [64][64]  Qs[d][r]
    float* Ks = Qs + QT * Dd;        // [64][64]  Ks[d][c]
    float* Vs = Ks + KT * Dd;        // [64][64]  Vs[c][d]
    float* Ps = Vs + KT * Dd;        // [64][68]  Ps[r][c]

    const int bh = blockIdx.y;
    const int b  = bh / Hh;
    const int h  = bh % Hh;
    const int qt = blockIdx.x;
    const int n0 = qt * QT;
    const int NQ = min(QT, Nn - n0);

    const int tid = threadIdx.x;
    const int tx = tid & 15, ty = tid >> 4;

    // ---- load Q tile: Qs[d][r] from g_qT[bh][d][n0+r], zero-fill r>=NQ ----
    {
        const int d = tid >> 2;              // 0..63
        const int r0 = (tid & 3) * 16;       // 0,16,32,48
        const float* src = g_qT + ((long)bh * Dd + d) * NPAD + n0;
        float* dst = Qs + d * QT;
        if (NQ == QT) {
#pragma unroll
            for (int s = 0; s < 16; s += 4)
                *(float4*)&dst[r0 + s] = *(const float4*)&src[r0 + s];
        } else {
#pragma unroll
            for (int s = 0; s < 16; s++) {
                int r = r0 + s;
                dst[r] = (r < NQ) ? src[r] : 0.f;
            }
        }
    }

    // per-row online softmax state (rows 4ty+i), redundant across tx lanes
    float m_i[4], l_i[4];
    float o[4][4];
#pragma unroll
    for (int i = 0; i < 4; i++) {
        m_i[i] = -1e30f; l_i[i] = 0.f;
#pragma unroll
        for (int j = 0; j < 4; j++) o[i][j] = 0.f;
    }

    for (int ch = 0; ch < NKT; ch++) {
        const int kc0 = ch * KT;
        const int KC = min(KT, Nn - kc0);

        __syncthreads();   // prior S-gemm / PV reads done before overwrite

        // ---- load K chunk: Ks[d][c], and V chunk: Vs[c][d] ----
        {
            const int d = tid >> 2;
            const int c0 = (tid & 3) * 16;
            const float* ksrc = g_kT + ((long)bh * Dd + d) * NPAD + kc0;
            float* kdst = Ks + d * KT;
            if (KC == KT) {
#pragma unroll
                for (int s = 0; s < 16; s += 4)
                    *(float4*)&kdst[c0 + s] = *(const float4*)&ksrc[c0 + s];
            } else {
#pragma unroll
                for (int s = 0; s < 16; s++) {
                    int c = c0 + s;
                    kdst[c] = (c < KC) ? ksrc[c] : 0.f;
                }
            }
            // V: row c = key, contiguous d
            const int c = tid >> 2;
            const int d0 = (tid & 3) * 16;
            float* vdst = Vs + c * Dd;
            if (c < KC) {
                const float* vsrc = g_v + ((long)bh * Nn + kc0 + c) * Dd;
#pragma unroll
                for (int s = 0; s < 16; s += 4)
                    *(float4*)&vdst[d0 + s] = *(const float4*)&vsrc[d0 + s];
            } else {
#pragma unroll
                for (int s = 0; s < 16; s += 4)
                    *(float4*)&vdst[d0 + s] = make_float4(0.f, 0.f, 0.f, 0.f);
            }
        }
        __syncthreads();

        // ---- S = Q·K^T (4x4 per thread) ----
        float s[4][4];
#pragma unroll
        for (int i = 0; i < 4; i++)
#pragma unroll
            for (int j = 0; j < 4; j++) s[i][j] = 0.f;

#pragma unroll 8
        for (int kk = 0; kk < Dd; kk++) {
            float4 a4 = *(float4*)&Qs[kk * QT + 4 * ty];
            float4 b4 = *(float4*)&Ks[kk * KT + 4 * tx];
            float af[4] = {a4.x, a4.y, a4.z, a4.w};
            float bf[4] = {b4.x, b4.y, b4.z, b4.w};
#pragma unroll
            for (int i = 0; i < 4; i++)
#pragma unroll
                for (int j = 0; j < 4; j++) s[i][j] = fmaf(af[i], bf[j], s[i][j]);
        }

        // scale + mask + CLS-row special handling
#pragma unroll
        for (int i = 0; i < 4; i++) {
#pragma unroll
            for (int j = 0; j < 4; j++) {
                int c = 4 * tx + j;
                float sv = s[i][j] * SCALEF;
                if (c >= KC) sv = -1e30f;
                s[i][j] = sv;
            }
        }
        if (qt == 0 && ty == 0) {
            // global row 0 = CLS row; owned by i==0 threads of ty==0
#pragma unroll
            for (int j = 0; j < 4; j++) {
                int mg = kc0 + 4 * tx + j;     // global key index
                if (mg >= 1 && mg < Nn) {
                    float sv = s[0][j];
                    patch[(long)bh * NPATCH + mg - 1] = sv;   // pre-reweight
                    float w = aw[(long)b * NPATCH + mg - 1];
                    s[0][j] = sv * (w * ALPHAF + (1.0f - ALPHAF));
                }
            }
        }

        // ---- online softmax update ----
#pragma unroll
        for (int i = 0; i < 4; i++) {
            float cm = fmaxf(fmaxf(s[i][0], s[i][1]), fmaxf(s[i][2], s[i][3]));
#pragma unroll
            for (int off = 8; off; off >>= 1)
                cm = fmaxf(cm, __shfl_xor_sync(0xffffffffu, cm, off));
            float mn = fmaxf(m_i[i], cm);
            float f = __expf(m_i[i] - mn);
            float rs = 0.f;
#pragma unroll
            for (int j = 0; j < 4; j++) {
                float p = __expf(s[i][j] - mn);
                s[i][j] = p;
                rs += p;
            }
#pragma unroll
            for (int off = 8; off; off >>= 1)
                rs += __shfl_xor_sync(0xffffffffu, rs, off);
            l_i[i] = l_i[i] * f + rs;
            m_i[i] = mn;
#pragma unroll
            for (int j = 0; j < 4; j++) o[i][j] *= f;
            // store P row-major (float4 per row)
            *(float4*)&Ps[(4 * ty + i) * PSP + 4 * tx] =
                make_float4(s[i][0], s[i][1], s[i][2], s[i][3]);
        }
        __syncthreads();

        // ---- O += P·V ----
#pragma unroll 8
        for (int cc = 0; cc < KT; cc++) {
            float4 b4 = *(float4*)&Vs[cc * Dd + 4 * tx];
            float bf[4] = {b4.x, b4.y, b4.z, b4.w};
            float a0 = Ps[(4 * ty + 0) * PSP + cc];
            float a1 = Ps[(4 * ty + 1) * PSP + cc];
            float a2 = Ps[(4 * ty + 2) * PSP + cc];
            float a3 = Ps[(4 * ty + 3) * PSP + cc];
#pragma unroll
            for (int j = 0; j < 4; j++) {
                o[0][j] = fmaf(a0, bf[j], o[0][j]);
                o[1][j] = fmaf(a1, bf[j], o[1][j]);
                o[2][j] = fmaf(a2, bf[j], o[2][j]);
                o[3][j] = fmaf(a3, bf[j], o[3][j]);
            }
        }
    }

    // ---- write output: g_ao[b*Nn + n][h*64 + d] ----
#pragma unroll
    for (int i = 0; i < 4; i++) {
        int r = 4 * ty + i;
        if (r >= NQ) continue;
        float inv = 1.0f / l_i[i];
        float4 v4 = make_float4(o[i][0] * inv, o[i][1] * inv,
                                o[i][2] * inv, o[i][3] * inv);
        *(float4*)&g_ao[((long)(b * Nn + n0 + r)) * Cc + h * Dd + 4 * tx] = v4;
    }
}

// ---------------------------------------------------------------------------
// Proj GEMM: out = g_ao @ w_proj + b_proj  -> d_out[0 : MM*768]
// ---------------------------------------------------------------------------
__global__ __launch_bounds__(256) void sgemm_proj(
    const float* __restrict__ Bm,   // w_proj [768, 768]
    const float* __restrict__ bias,
    float* __restrict__ out)
{
    __shared__ float As[8][128];
    __shared__ float Bs[8][128];
    const int tid = threadIdx.x;
    const int rowBase = blockIdx.y * 128;
    const int colBase = blockIdx.x * 128;
    const int tx = tid & 15, ty = tid >> 4;

    float acc[8][8];
#pragma unroll
    for (int i = 0; i < 8; i++)
#pragma unroll
        for (int j = 0; j < 8; j++) acc[i][j] = 0.f;

    const int arow = tid >> 1, aseg = (tid & 1) * 4;
    const int brow = tid >> 5, bcol = (tid & 31) * 4;

    for (int k0 = 0; k0 < KDIM; k0 += 8) {
        float4 a4 = make_float4(0.f, 0.f, 0.f, 0.f);
        int gr = rowBase + arow;
        if (gr < MM) a4 = *(const float4*)(g_ao + (long)gr * KDIM + k0 + aseg);
        As[aseg + 0][arow] = a4.x;
        As[aseg + 1][arow] = a4.y;
        As[aseg + 2][arow] = a4.z;
        As[aseg + 3][arow] = a4.w;

        float4 b4 = *(const float4*)(Bm + (long)(k0 + brow) * Cc + colBase + bcol);
        *(float4*)&Bs[brow][bcol] = b4;
        __syncthreads();

#pragma unroll
        for (int kk = 0; kk < 8; kk++) {
            float4 a0 = *(float4*)&As[kk][ty * 8];
            float4 a1 = *(float4*)&As[kk][ty * 8 + 4];
            float4 b0 = *(float4*)&Bs[kk][tx * 8];
            float4 b1 = *(float4*)&Bs[kk][tx * 8 + 4];
            float af[8] = {a0.x, a0.y, a0.z, a0.w, a1.x, a1.y, a1.z, a1.w};
            float bf[8] = {b0.x, b0.y, b0.z, b0.w, b1.x, b1.y, b1.z, b1.w};
#pragma unroll
            for (int i = 0; i < 8; i++)
#pragma unroll
                for (int j = 0; j < 8; j++) acc[i][j] = fmaf(af[i], bf[j], acc[i][j]);
        }
        __syncthreads();
    }

#pragma unroll
    for (int i = 0; i < 8; i++) {
        int gr = rowBase + ty * 8 + i;
        if (gr >= MM) continue;
#pragma unroll
        for (int j = 0; j < 8; j++) {
            int col = colBase + tx * 8 + j;
            out[(long)gr * Cc + col] = acc[i][j] + bias[col];
        }
    }
}

// ---------------------------------------------------------------------------
extern "C" void kernel_launch(void* const* d_in, const int* in_sizes, int n_in,
                              void* d_out, int out_size)
{
    const float* x      = (const float*)d_in[0];
    const float* aw     = (const float*)d_in[1];
    const float* w_qkv  = (const float*)d_in[2];
    const float* b_qkv  = (const float*)d_in[3];
    const float* w_proj = (const float*)d_in[4];
    const float* b_proj = (const float*)d_in[5];

    float* out   = (float*)d_out;
    float* patch = out + (long)Bb * Nn * Cc;   // patch_attn after main output

    dim3 gq(QKVN / 128, (MM + 127) / 128);     // 18 x 73
    sgemm_qkv<<<gq, 256>>>(x, w_qkv, b_qkv);

    const int smem_attn = (QT * Dd + KT * Dd + KT * Dd + QT * PSP) * (int)sizeof(float);
    cudaFuncSetAttribute(attn_flash, cudaFuncAttributeMaxDynamicSharedMemorySize, smem_attn);
    dim3 ga(NQT, Bb * Hh);                     // 10 x 192
    attn_flash<<<ga, 256, smem_attn>>>(aw, patch);

    dim3 gp(Cc / 128, (MM + 127) / 128);       // 6 x 73
    sgemm_proj<<<gp, 256>>>(w_proj, b_proj, out);
}

// round 7
// speedup vs baseline: 2.9271x; 1.5042x over previous
#include <cuda_runtime.h>

// Problem constants
#define Bb 16
#define Nn 577
#define Cc 768
#define Hh 12
#define Dd 64
#define SCALEF 0.125f
#define ALPHAF 0.1f
#define MM (Bb * Nn)        // 9232 rows
#define QKVN (3 * Cc)       // 2304
#define KDIM 768
#define NPATCH (Nn - 1)     // 576
#define NPAD 580            // Nn padded to multiple of 4 (16B-aligned rows)

// Scratch (static device globals — no allocation allowed in kernel_launch)
__device__ float g_qT[Bb * Hh * Dd * NPAD];  // [bh][d][NPAD]
__device__ float g_kT[Bb * Hh * Dd * NPAD];  // [bh][d][NPAD]
__device__ float g_v [Bb * Hh * Nn * Dd];    // [bh][n][d]
__device__ float g_ao[Bb * Nn * Cc];

// ---------------------------------------------------------------------------
// QKV GEMM: y = x @ w_qkv + b_qkv, scattered into qT/kT (d-major) and v.
// ---------------------------------------------------------------------------
__global__ __launch_bounds__(256) void sgemm_qkv(
    const float* __restrict__ A,   // x      [MM, 768]
    const float* __restrict__ Bm,  // w_qkv  [768, 2304]
    const float* __restrict__ bias)
{
    __shared__ float As[8][128];
    __shared__ float Bs[8][128];
    const int tid = threadIdx.x;
    const int rowBase = blockIdx.y * 128;
    const int colBase = blockIdx.x * 128;
    const int tx = tid & 15, ty = tid >> 4;

    float acc[8][8];
#pragma unroll
    for (int i = 0; i < 8; i++)
#pragma unroll
        for (int j = 0; j < 8; j++) acc[i][j] = 0.f;

    const int arow = tid >> 1, aseg = (tid & 1) * 4;
    const int brow = tid >> 5, bcol = (tid & 31) * 4;

    for (int k0 = 0; k0 < KDIM; k0 += 8) {
        float4 a4 = make_float4(0.f, 0.f, 0.f, 0.f);
        int gr = rowBase + arow;
        if (gr < MM) a4 = *(const float4*)(A + (long)gr * KDIM + k0 + aseg);
        As[aseg + 0][arow] = a4.x;
        As[aseg + 1][arow] = a4.y;
        As[aseg + 2][arow] = a4.z;
        As[aseg + 3][arow] = a4.w;

        float4 b4 = *(const float4*)(Bm + (long)(k0 + brow) * QKVN + colBase + bcol);
        *(float4*)&Bs[brow][bcol] = b4;
        __syncthreads();

#pragma unroll
        for (int kk = 0; kk < 8; kk++) {
            float4 a0 = *(float4*)&As[kk][ty * 8];
            float4 a1 = *(float4*)&As[kk][ty * 8 + 4];
            float4 b0 = *(float4*)&Bs[kk][tx * 8];
            float4 b1 = *(float4*)&Bs[kk][tx * 8 + 4];
            float af[8] = {a0.x, a0.y, a0.z, a0.w, a1.x, a1.y, a1.z, a1.w};
            float bf[8] = {b0.x, b0.y, b0.z, b0.w, b1.x, b1.y, b1.z, b1.w};
#pragma unroll
            for (int i = 0; i < 8; i++)
#pragma unroll
                for (int j = 0; j < 8; j++) acc[i][j] = fmaf(af[i], bf[j], acc[i][j]);
        }
        __syncthreads();
    }

#pragma unroll
    for (int i = 0; i < 8; i++) {
        int gr = rowBase + ty * 8 + i;
        if (gr >= MM) continue;
        int bidx = gr / Nn, n = gr % Nn;
#pragma unroll
        for (int j = 0; j < 8; j++) {
            int col = colBase + tx * 8 + j;
            float val = acc[i][j] + bias[col];
            int which = col / Cc;          // 0=q 1=k 2=v (constant per 128-tile)
            int c = col % Cc;
            int h = c >> 6, d = c & 63;
            long bh = (long)bidx * Hh + h;
            if (which == 0)      g_qT[(bh * Dd + d) * NPAD + n] = val;
            else if (which == 1) g_kT[(bh * Dd + d) * NPAD + n] = val;
            else                 g_v [(bh * Nn + n) * Dd + d] = val;
        }
    }
}

// ---------------------------------------------------------------------------
// Flash-style attention v2: block = 128 q-rows of one (b,h); 256 threads.
// Thread (tx,ty) owns 8 rows (8ty..8ty+7) x 4 cols (4tx..4tx+3) in both
// S=QK^T and O=PV (same rows -> softmax state in regs, reduced over 16 lanes).
// ---------------------------------------------------------------------------
#define QT 128
#define KT 64
#define NQT ((Nn + QT - 1) / QT)   // 5
#define NKT ((Nn + KT - 1) / KT)   // 10
#define PSP 68                     // Ps pitch (floats): 16B-aligned, bank-spread

__global__ __launch_bounds__(256, 2) void attn_flash(
    const float* __restrict__ aw,   // attn_weight [B, 576]
    float* __restrict__ patch)      // [B*H, 576]
{
    extern __shared__ float sm[];
    float* Qs = sm;                  // [64][128] Qs[d][r]
    float* Ks = Qs + Dd * QT;        // [64][64]  Ks[d][c]
    float* Vs = Ks + Dd * KT;        // [64][64]  Vs[c][d]
    float* Ps = Vs + KT * Dd;        // [128][68] Ps[r][c]

    const int bh = blockIdx.y;
    const int b  = bh / Hh;
    const int h  = bh % Hh;
    const int qt = blockIdx.x;
    const int n0 = qt * QT;
    const int NQ = min(QT, Nn - n0);

    const int tid = threadIdx.x;
    const int tx = tid & 15, ty = tid >> 4;

    // ---- load Q tile: Qs[d][r] from g_qT[bh][d][n0+r], zero-fill r>=NQ ----
    {
        const int d = tid >> 2;              // 0..63
        const int r0 = (tid & 3) * 32;       // 0,32,64,96
        const float* src = g_qT + ((long)bh * Dd + d) * NPAD + n0;
        float* dst = Qs + d * QT;
        if (NQ == QT) {
#pragma unroll
            for (int s = 0; s < 32; s += 4)
                *(float4*)&dst[r0 + s] = *(const float4*)&src[r0 + s];
        } else {
#pragma unroll
            for (int s = 0; s < 32; s++) {
                int r = r0 + s;
                dst[r] = (r < NQ) ? src[r] : 0.f;
            }
        }
    }

    // per-row online softmax state (rows 8ty+i), redundant across tx lanes
    float m_i[8], l_i[8];
    float o[8][4];
#pragma unroll
    for (int i = 0; i < 8; i++) {
        m_i[i] = -1e30f; l_i[i] = 0.f;
#pragma unroll
        for (int j = 0; j < 4; j++) o[i][j] = 0.f;
    }

    for (int ch = 0; ch < NKT; ch++) {
        const int kc0 = ch * KT;
        const int KC = min(KT, Nn - kc0);

        __syncthreads();   // prior S-gemm / PV reads done before overwrite

        // ---- load K chunk: Ks[d][c], and V chunk: Vs[c][d] ----
        {
            const int d = tid >> 2;
            const int c0 = (tid & 3) * 16;
            const float* ksrc = g_kT + ((long)bh * Dd + d) * NPAD + kc0;
            float* kdst = Ks + d * KT;
            if (KC == KT) {
#pragma unroll
                for (int s = 0; s < 16; s += 4)
                    *(float4*)&kdst[c0 + s] = *(const float4*)&ksrc[c0 + s];
            } else {
#pragma unroll
                for (int s = 0; s < 16; s++) {
                    int c = c0 + s;
                    kdst[c] = (c < KC) ? ksrc[c] : 0.f;
                }
            }
            // V: row c = key, contiguous d
            const int c = tid >> 2;
            const int d0 = (tid & 3) * 16;
            float* vdst = Vs + c * Dd;
            if (c < KC) {
                const float* vsrc = g_v + ((long)bh * Nn + kc0 + c) * Dd;
#pragma unroll
                for (int s = 0; s < 16; s += 4)
                    *(float4*)&vdst[d0 + s] = *(const float4*)&vsrc[d0 + s];
            } else {
#pragma unroll
                for (int s = 0; s < 16; s += 4)
                    *(float4*)&vdst[d0 + s] = make_float4(0.f, 0.f, 0.f, 0.f);
            }
        }
        __syncthreads();

        // ---- S = Q·K^T (8x4 per thread) ----
        float s[8][4];
#pragma unroll
        for (int i = 0; i < 8; i++)
#pragma unroll
            for (int j = 0; j < 4; j++) s[i][j] = 0.f;

#pragma unroll 4
        for (int kk = 0; kk < Dd; kk++) {
            float4 a0 = *(float4*)&Qs[kk * QT + 8 * ty];
            float4 a1 = *(float4*)&Qs[kk * QT + 8 * ty + 4];
            float4 b4 = *(float4*)&Ks[kk * KT + 4 * tx];
            float af[8] = {a0.x, a0.y, a0.z, a0.w, a1.x, a1.y, a1.z, a1.w};
            float bf[4] = {b4.x, b4.y, b4.z, b4.w};
#pragma unroll
            for (int i = 0; i < 8; i++)
#pragma unroll
                for (int j = 0; j < 4; j++) s[i][j] = fmaf(af[i], bf[j], s[i][j]);
        }

        // scale + mask
#pragma unroll
        for (int i = 0; i < 8; i++)
#pragma unroll
            for (int j = 0; j < 4; j++) {
                int c = 4 * tx + j;
                float sv = s[i][j] * SCALEF;
                if (c >= KC) sv = -1e30f;
                s[i][j] = sv;
            }

        // CLS-row handling: global row 0 lives in qt==0, ty==0, i==0
        if (qt == 0 && ty == 0) {
#pragma unroll
            for (int j = 0; j < 4; j++) {
                int mg = kc0 + 4 * tx + j;     // global key index
                if (mg >= 1 && mg < Nn) {
                    float sv = s[0][j];
                    patch[(long)bh * NPATCH + mg - 1] = sv;   // pre-reweight
                    float w = aw[(long)b * NPATCH + mg - 1];
                    s[0][j] = sv * (w * ALPHAF + (1.0f - ALPHAF));
                }
            }
        }

        // ---- online softmax update (per owned row) ----
#pragma unroll
        for (int i = 0; i < 8; i++) {
            float cm = fmaxf(fmaxf(s[i][0], s[i][1]), fmaxf(s[i][2], s[i][3]));
#pragma unroll
            for (int off = 8; off; off >>= 1)
                cm = fmaxf(cm, __shfl_xor_sync(0xffffffffu, cm, off));
            float mn = fmaxf(m_i[i], cm);
            float f = __expf(m_i[i] - mn);
            float rs = 0.f;
#pragma unroll
            for (int j = 0; j < 4; j++) {
                float p = __expf(s[i][j] - mn);
                s[i][j] = p;
                rs += p;
            }
#pragma unroll
            for (int off = 8; off; off >>= 1)
                rs += __shfl_xor_sync(0xffffffffu, rs, off);
            l_i[i] = l_i[i] * f + rs;
            m_i[i] = mn;
#pragma unroll
            for (int j = 0; j < 4; j++) o[i][j] *= f;
            *(float4*)&Ps[(8 * ty + i) * PSP + 4 * tx] =
                make_float4(s[i][0], s[i][1], s[i][2], s[i][3]);
        }
        __syncthreads();

        // ---- O += P·V (8 rows x 4 d-cols per thread) ----
#pragma unroll 4
        for (int cc = 0; cc < KT; cc++) {
            float4 b4 = *(float4*)&Vs[cc * Dd + 4 * tx];
            float bf[4] = {b4.x, b4.y, b4.z, b4.w};
            float a[8];
#pragma unroll
            for (int i = 0; i < 8; i++) a[i] = Ps[(8 * ty + i) * PSP + cc];
#pragma unroll
            for (int i = 0; i < 8; i++)
#pragma unroll
                for (int j = 0; j < 4; j++) o[i][j] = fmaf(a[i], bf[j], o[i][j]);
        }
    }

    // ---- write output: g_ao[b*Nn + n][h*64 + d] ----
#pragma unroll
    for (int i = 0; i < 8; i++) {
        int r = 8 * ty + i;
        if (r >= NQ) continue;
        float inv = 1.0f / l_i[i];
        float4 v4 = make_float4(o[i][0] * inv, o[i][1] * inv,
                                o[i][2] * inv, o[i][3] * inv);
        *(float4*)&g_ao[((long)(b * Nn + n0 + r)) * Cc + h * Dd + 4 * tx] = v4;
    }
}

// ---------------------------------------------------------------------------
// Proj GEMM: out = g_ao @ w_proj + b_proj  -> d_out[0 : MM*768]
// ---------------------------------------------------------------------------
__global__ __launch_bounds__(256) void sgemm_proj(
    const float* __restrict__ Bm,   // w_proj [768, 768]
    const float* __restrict__ bias,
    float* __restrict__ out)
{
    __shared__ float As[8][128];
    __shared__ float Bs[8][128];
    const int tid = threadIdx.x;
    const int rowBase = blockIdx.y * 128;
    const int colBase = blockIdx.x * 128;
    const int tx = tid & 15, ty = tid >> 4;

    float acc[8][8];
#pragma unroll
    for (int i = 0; i < 8; i++)
#pragma unroll
        for (int j = 0; j < 8; j++) acc[i][j] = 0.f;

    const int arow = tid >> 1, aseg = (tid & 1) * 4;
    const int brow = tid >> 5, bcol = (tid & 31) * 4;

    for (int k0 = 0; k0 < KDIM; k0 += 8) {
        float4 a4 = make_float4(0.f, 0.f, 0.f, 0.f);
        int gr = rowBase + arow;
        if (gr < MM) a4 = *(const float4*)(g_ao + (long)gr * KDIM + k0 + aseg);
        As[aseg + 0][arow] = a4.x;
        As[aseg + 1][arow] = a4.y;
        As[aseg + 2][arow] = a4.z;
        As[aseg + 3][arow] = a4.w;

        float4 b4 = *(const float4*)(Bm + (long)(k0 + brow) * Cc + colBase + bcol);
        *(float4*)&Bs[brow][bcol] = b4;
        __syncthreads();

#pragma unroll
        for (int kk = 0; kk < 8; kk++) {
            float4 a0 = *(float4*)&As[kk][ty * 8];
            float4 a1 = *(float4*)&As[kk][ty * 8 + 4];
            float4 b0 = *(float4*)&Bs[kk][tx * 8];
            float4 b1 = *(float4*)&Bs[kk][tx * 8 + 4];
            float af[8] = {a0.x, a0.y, a0.z, a0.w, a1.x, a1.y, a1.z, a1.w};
            float bf[8] = {b0.x, b0.y, b0.z, b0.w, b1.x, b1.y, b1.z, b1.w};
#pragma unroll
            for (int i = 0; i < 8; i++)
#pragma unroll
                for (int j = 0; j < 8; j++) acc[i][j] = fmaf(af[i], bf[j], acc[i][j]);
        }
        __syncthreads();
    }

#pragma unroll
    for (int i = 0; i < 8; i++) {
        int gr = rowBase + ty * 8 + i;
        if (gr >= MM) continue;
#pragma unroll
        for (int j = 0; j < 8; j++) {
            int col = colBase + tx * 8 + j;
            out[(long)gr * Cc + col] = acc[i][j] + bias[col];
        }
    }
}

// ---------------------------------------------------------------------------
extern "C" void kernel_launch(void* const* d_in, const int* in_sizes, int n_in,
                              void* d_out, int out_size)
{
    const float* x      = (const float*)d_in[0];
    const float* aw     = (const float*)d_in[1];
    const float* w_qkv  = (const float*)d_in[2];
    const float* b_qkv  = (const float*)d_in[3];
    const float* w_proj = (const float*)d_in[4];
    const float* b_proj = (const float*)d_in[5];

    float* out   = (float*)d_out;
    float* patch = out + (long)Bb * Nn * Cc;   // patch_attn after main output

    dim3 gq(QKVN / 128, (MM + 127) / 128);     // 18 x 73
    sgemm_qkv<<<gq, 256>>>(x, w_qkv, b_qkv);

    const int smem_attn = (Dd * QT + Dd * KT + KT * Dd + QT * PSP) * (int)sizeof(float);
    cudaFuncSetAttribute(attn_flash, cudaFuncAttributeMaxDynamicSharedMemorySize, smem_attn);
    dim3 ga(NQT, Bb * Hh);                     // 5 x 192
    attn_flash<<<ga, 256, smem_attn>>>(aw, patch);

    dim3 gp(Cc / 128, (MM + 127) / 128);       // 6 x 73
    sgemm_proj<<<gp, 256>>>(w_proj, b_proj, out);
}

// round 10
// speedup vs baseline: 5.4270x; 1.8541x over previous
#include <cuda_runtime.h>
#include <cuda_bf16.h>
#include <cstdint>

// Problem constants
#define Bb 16
#define Nn 577
#define Cc 768
#define Hh 12
#define Dd 64
#define SCALEF 0.125f
#define ALPHAF 0.1f
#define MM (Bb * Nn)        // 9232 rows
#define QKVN (3 * Cc)       // 2304
#define KDIM 768
#define NPATCH (Nn - 1)     // 576
#define NPAD 580            // Nn padded to multiple of 4 (16B-aligned rows)

// Scratch (static device globals — no allocation allowed in kernel_launch).
// NOTE: these must ONLY be referenced from device code. Passing them as kernel
// arguments from host passes the host shadow address (which GB300 ATS happily
// dereferences as host memory -> silent zeros). That was the R8/R9 bug.
__device__ float g_qT[Bb * Hh * Dd * NPAD];  // [bh][d][NPAD]
__device__ float g_kT[Bb * Hh * Dd * NPAD];  // [bh][d][NPAD]
__device__ float g_v [Bb * Hh * Nn * Dd];    // [bh][n][d]
__device__ float g_ao[Bb * Nn * Cc];

// ===========================================================================
// bf16 split-precision tensor-core GEMM (mma.sync.m16n8k16)
// C = A(fp32) @ B(fp32): A=Ahi+Alo, B=Bhi+Blo; C ≈ AhiBhi + AhiBlo + AloBhi
// Block tile 128x128, k-tile 32, SINGLE smem stage (37.9KB < 48KB),
// LDG register prefetch overlaps compute. 8 warps, 64x32 warp tiles.
// ===========================================================================
#define APITCH 40    // bf16 elems per A smem row (32 + 8 pad) -> 80 B
#define BPITCH 136   // bf16 elems per B smem row (128 + 8 pad) -> 272 B
#define STAGE_ELEMS (128 * APITCH * 2 + 32 * BPITCH * 2)   // 18944 bf16
#define GEMM_SMEM (STAGE_ELEMS * 2)                        // 37888 bytes

__device__ __forceinline__ uint32_t smem_u32(const void* p) {
    return (uint32_t)__cvta_generic_to_shared(p);
}
__device__ __forceinline__ void ldsm4(uint32_t r[4], uint32_t addr) {
    asm volatile("ldmatrix.sync.aligned.m8n8.x4.shared.b16 {%0,%1,%2,%3}, [%4];"
        : "=r"(r[0]), "=r"(r[1]), "=r"(r[2]), "=r"(r[3]) : "r"(addr));
}
__device__ __forceinline__ void ldsm4t(uint32_t r[4], uint32_t addr) {
    asm volatile("ldmatrix.sync.aligned.m8n8.x4.trans.shared.b16 {%0,%1,%2,%3}, [%4];"
        : "=r"(r[0]), "=r"(r[1]), "=r"(r[2]), "=r"(r[3]) : "r"(addr));
}
__device__ __forceinline__ void mma16816(float c[4], const uint32_t a[4],
                                         uint32_t b0, uint32_t b1) {
    asm volatile(
        "mma.sync.aligned.m16n8k16.row.col.f32.bf16.bf16.f32 "
        "{%0,%1,%2,%3}, {%4,%5,%6,%7}, {%8,%9}, {%0,%1,%2,%3};"
        : "+f"(c[0]), "+f"(c[1]), "+f"(c[2]), "+f"(c[3])
        : "r"(a[0]), "r"(a[1]), "r"(a[2]), "r"(a[3]), "r"(b0), "r"(b1));
}
__device__ __forceinline__ uint32_t pack_hi(float x, float y,
                                            float& lx, float& ly) {
    __nv_bfloat16 hx = __float2bfloat16(x);
    __nv_bfloat16 hy = __float2bfloat16(y);
    lx = x - __bfloat162float(hx);
    ly = y - __bfloat162float(hy);
    __nv_bfloat162 p{hx, hy};
    return *(uint32_t*)&p;
}
__device__ __forceinline__ uint32_t pack_bf2(float x, float y) {
    __nv_bfloat162 p{__float2bfloat16(x), __float2bfloat16(y)};
    return *(uint32_t*)&p;
}

extern __shared__ unsigned char dynsm[];

// EPI: 0 = qkv (A = x param, scatter epilogue), 1 = proj (A = g_ao device
// global resolved IN DEVICE CODE, bias + store to out)
template <int EPI>
__global__ __launch_bounds__(256) void gemm_bf16s(
    const float* __restrict__ Ain,  // [MM, 768] row-major (EPI==0 only)
    const float* __restrict__ Bg,   // [768, ldb] row-major
    const float* __restrict__ bias, // [ldb]
    float* __restrict__ out,        // proj only
    int ldb)
{
    // Device-side source select: g_ao must be referenced from device code.
    const float* __restrict__ A = (EPI == 1) ? (const float*)g_ao : Ain;

    __nv_bfloat16* sm = (__nv_bfloat16*)dynsm;
    const int tid  = threadIdx.x;
    const int lane = tid & 31, warp = tid >> 5;
    const int rowBase = blockIdx.y * 128;
    const int colBase = blockIdx.x * 128;
    const int wm0 = (warp >> 2) * 64;      // 0 or 64
    const int wn0 = (warp & 3) * 32;       // 0,32,64,96

    __nv_bfloat16* Ahi = sm;
    __nv_bfloat16* Alo = sm + 128 * APITCH;
    __nv_bfloat16* Bhi = sm + 256 * APITCH;
    __nv_bfloat16* Blo = sm + 256 * APITCH + 32 * BPITCH;

    // LDG staging assignment
    const int aRow = tid >> 3;              // 0..31
    const int aK4  = (tid & 7) * 4;         // 0..28
    const int bK   = tid >> 5;              // 0..7
    const int bN4  = (tid & 31) * 4;        // 0..124

    float4 ar[4], br[4];
    auto do_load = [&](int k0) {
#pragma unroll
        for (int p = 0; p < 4; p++) {
            int gr = rowBase + aRow + 32 * p;
            ar[p] = (gr < MM) ? *(const float4*)(A + (long)gr * KDIM + k0 + aK4)
                              : make_float4(0.f, 0.f, 0.f, 0.f);
        }
#pragma unroll
        for (int p = 0; p < 4; p++)
            br[p] = *(const float4*)(Bg + (long)(k0 + bK + 8 * p) * ldb + colBase + bN4);
    };
    auto do_sts = [&]() {
#pragma unroll
        for (int p = 0; p < 4; p++) {
            int base = (aRow + 32 * p) * APITCH + aK4;
            float lx, ly, lz, lw;
            uint32_t h01 = pack_hi(ar[p].x, ar[p].y, lx, ly);
            uint32_t h23 = pack_hi(ar[p].z, ar[p].w, lz, lw);
            *(uint2*)&Ahi[base] = make_uint2(h01, h23);
            *(uint2*)&Alo[base] = make_uint2(pack_bf2(lx, ly), pack_bf2(lz, lw));
        }
#pragma unroll
        for (int p = 0; p < 4; p++) {
            int base = (bK + 8 * p) * BPITCH + bN4;
            float lx, ly, lz, lw;
            uint32_t h01 = pack_hi(br[p].x, br[p].y, lx, ly);
            uint32_t h23 = pack_hi(br[p].z, br[p].w, lz, lw);
            *(uint2*)&Bhi[base] = make_uint2(h01, h23);
            *(uint2*)&Blo[base] = make_uint2(pack_bf2(lx, ly), pack_bf2(lz, lw));
        }
    };

    float acc[4][4][4];
#pragma unroll
    for (int mi = 0; mi < 4; mi++)
#pragma unroll
        for (int j = 0; j < 4; j++)
#pragma unroll
            for (int r = 0; r < 4; r++) acc[mi][j][r] = 0.f;

    // per-lane ldmatrix address components (bytes)
    const int aOff = (wm0 + (lane & 15)) * (APITCH * 2) + (lane >> 4) * 16;
    const int bOff = (lane & 15) * (BPITCH * 2) + (wn0 + ((lane >> 4) << 3)) * 2;
    const uint32_t aHiB = smem_u32(Ahi) + aOff;
    const uint32_t aLoB = smem_u32(Alo) + aOff;
    const uint32_t bHiB = smem_u32(Bhi) + bOff;
    const uint32_t bLoB = smem_u32(Blo) + bOff;

    do_load(0);

#pragma unroll 1
    for (int t = 0; t < KDIM / 32; t++) {
        __syncthreads();        // prior compute's smem reads complete
        do_sts();
        __syncthreads();
        if (t + 1 < KDIM / 32) do_load((t + 1) * 32);   // prefetch into regs

#pragma unroll
        for (int ks = 0; ks < 2; ks++) {
            uint32_t ah[4][4], al[4][4], bh[2][4], bl[2][4];
#pragma unroll
            for (int mi = 0; mi < 4; mi++) {
                ldsm4(ah[mi], aHiB + mi * (16 * APITCH * 2) + ks * 32);
                ldsm4(al[mi], aLoB + mi * (16 * APITCH * 2) + ks * 32);
            }
#pragma unroll
            for (int nb = 0; nb < 2; nb++) {
                ldsm4t(bh[nb], bHiB + nb * 32 + ks * (16 * BPITCH * 2));
                ldsm4t(bl[nb], bLoB + nb * 32 + ks * (16 * BPITCH * 2));
            }
#pragma unroll
            for (int mi = 0; mi < 4; mi++)
#pragma unroll
                for (int j = 0; j < 4; j++) {
                    const int nb = j >> 1, hf = (j & 1) * 2;
                    mma16816(acc[mi][j], ah[mi], bh[nb][hf], bh[nb][hf + 1]);
                    mma16816(acc[mi][j], ah[mi], bl[nb][hf], bl[nb][hf + 1]);
                    mma16816(acc[mi][j], al[mi], bh[nb][hf], bh[nb][hf + 1]);
                }
        }
    }

    // ---- epilogue ----
#pragma unroll
    for (int mi = 0; mi < 4; mi++) {
        const int r0 = wm0 + mi * 16 + (lane >> 2);
#pragma unroll
        for (int half = 0; half < 2; half++) {   // rows r0, r0+8
            const int r = r0 + half * 8;
            const int gr = rowBase + r;
            if (gr >= MM) continue;
            if (EPI == 0) {
                const int bidx = gr / Nn, n = gr % Nn;
#pragma unroll
                for (int j = 0; j < 4; j++) {
                    const int c0 = wn0 + j * 8 + (lane & 3) * 2;
#pragma unroll
                    for (int e = 0; e < 2; e++) {
                        const int gc = colBase + c0 + e;
                        float v = acc[mi][j][half * 2 + e] + bias[gc];
                        const int which = gc / Cc;
                        const int cc = gc % Cc;
                        const int h = cc >> 6, d = cc & 63;
                        const long bh_ = (long)bidx * Hh + h;
                        if (which == 0)      g_qT[(bh_ * Dd + d) * NPAD + n] = v;
                        else if (which == 1) g_kT[(bh_ * Dd + d) * NPAD + n] = v;
                        else                 g_v [(bh_ * Nn + n) * Dd + d] = v;
                    }
                }
            } else {
#pragma unroll
                for (int j = 0; j < 4; j++) {
                    const int c0 = wn0 + j * 8 + (lane & 3) * 2;
                    const int gc = colBase + c0;
                    float2 v2 = make_float2(acc[mi][j][half * 2 + 0] + bias[gc],
                                            acc[mi][j][half * 2 + 1] + bias[gc + 1]);
                    *(float2*)&out[(long)gr * Cc + gc] = v2;
                }
            }
        }
    }
}

// ---------------------------------------------------------------------------
// Flash-style attention: block = 128 q-rows of one (b,h); 256 threads.
// Thread (tx,ty) owns 8 rows x 4 cols in both S=QK^T and O=PV.
// ---------------------------------------------------------------------------
#define QT 128
#define KT 64
#define NQT ((Nn + QT - 1) / QT)   // 5
#define NKT ((Nn + KT - 1) / KT)   // 10
#define PSP 68                     // Ps pitch (floats): 16B-aligned, bank-spread

__global__ __launch_bounds__(256, 2) void attn_flash(
    const float* __restrict__ aw,   // attn_weight [B, 576]
    float* __restrict__ patch)      // [B*H, 576]
{
    float* smf = (float*)dynsm;
    float* Qs = smf;                 // [64][128] Qs[d][r]
    float* Ks = Qs + Dd * QT;        // [64][64]  Ks[d][c]
    float* Vs = Ks + Dd * KT;        // [64][64]  Vs[c][d]
    float* Ps = Vs + KT * Dd;        // [128][68] Ps[r][c]

    const int bh = blockIdx.y;
    const int b  = bh / Hh;
    const int h  = bh % Hh;
    const int qt = blockIdx.x;
    const int n0 = qt * QT;
    const int NQ = min(QT, Nn - n0);

    const int tid = threadIdx.x;
    const int tx = tid & 15, ty = tid >> 4;

    // ---- load Q tile ----
    {
        const int d = tid >> 2;
        const int r0 = (tid & 3) * 32;
        const float* src = g_qT + ((long)bh * Dd + d) * NPAD + n0;
        float* dst = Qs + d * QT;
        if (NQ == QT) {
#pragma unroll
            for (int s = 0; s < 32; s += 4)
                *(float4*)&dst[r0 + s] = *(const float4*)&src[r0 + s];
        } else {
#pragma unroll
            for (int s = 0; s < 32; s++) {
                int r = r0 + s;
                dst[r] = (r < NQ) ? src[r] : 0.f;
            }
        }
    }

    float m_i[8], l_i[8];
    float o[8][4];
#pragma unroll
    for (int i = 0; i < 8; i++) {
        m_i[i] = -1e30f; l_i[i] = 0.f;
#pragma unroll
        for (int j = 0; j < 4; j++) o[i][j] = 0.f;
    }

    for (int ch = 0; ch < NKT; ch++) {
        const int kc0 = ch * KT;
        const int KC = min(KT, Nn - kc0);

        __syncthreads();

        {
            const int d = tid >> 2;
            const int c0 = (tid & 3) * 16;
            const float* ksrc = g_kT + ((long)bh * Dd + d) * NPAD + kc0;
            float* kdst = Ks + d * KT;
            if (KC == KT) {
#pragma unroll
                for (int s = 0; s < 16; s += 4)
                    *(float4*)&kdst[c0 + s] = *(const float4*)&ksrc[c0 + s];
            } else {
#pragma unroll
                for (int s = 0; s < 16; s++) {
                    int c = c0 + s;
                    kdst[c] = (c < KC) ? ksrc[c] : 0.f;
                }
            }
            const int c = tid >> 2;
            const int d0 = (tid & 3) * 16;
            float* vdst = Vs + c * Dd;
            if (c < KC) {
                const float* vsrc = g_v + ((long)bh * Nn + kc0 + c) * Dd;
#pragma unroll
                for (int s = 0; s < 16; s += 4)
                    *(float4*)&vdst[d0 + s] = *(const float4*)&vsrc[d0 + s];
            } else {
#pragma unroll
                for (int s = 0; s < 16; s += 4)
                    *(float4*)&vdst[d0 + s] = make_float4(0.f, 0.f, 0.f, 0.f);
            }
        }
        __syncthreads();

        float s[8][4];
#pragma unroll
        for (int i = 0; i < 8; i++)
#pragma unroll
            for (int j = 0; j < 4; j++) s[i][j] = 0.f;

#pragma unroll 4
        for (int kk = 0; kk < Dd; kk++) {
            float4 a0 = *(float4*)&Qs[kk * QT + 8 * ty];
            float4 a1 = *(float4*)&Qs[kk * QT + 8 * ty + 4];
            float4 b4 = *(float4*)&Ks[kk * KT + 4 * tx];
            float af[8] = {a0.x, a0.y, a0.z, a0.w, a1.x, a1.y, a1.z, a1.w};
            float bf[4] = {b4.x, b4.y, b4.z, b4.w};
#pragma unroll
            for (int i = 0; i < 8; i++)
#pragma unroll
                for (int j = 0; j < 4; j++) s[i][j] = fmaf(af[i], bf[j], s[i][j]);
        }

#pragma unroll
        for (int i = 0; i < 8; i++)
#pragma unroll
            for (int j = 0; j < 4; j++) {
                int c = 4 * tx + j;
                float sv = s[i][j] * SCALEF;
                if (c >= KC) sv = -1e30f;
                s[i][j] = sv;
            }

        if (qt == 0 && ty == 0) {
#pragma unroll
            for (int j = 0; j < 4; j++) {
                int mg = kc0 + 4 * tx + j;
                if (mg >= 1 && mg < Nn) {
                    float sv = s[0][j];
                    patch[(long)bh * NPATCH + mg - 1] = sv;
                    float w = aw[(long)b * NPATCH + mg - 1];
                    s[0][j] = sv * (w * ALPHAF + (1.0f - ALPHAF));
                }
            }
        }

#pragma unroll
        for (int i = 0; i < 8; i++) {
            float cm = fmaxf(fmaxf(s[i][0], s[i][1]), fmaxf(s[i][2], s[i][3]));
#pragma unroll
            for (int off = 8; off; off >>= 1)
                cm = fmaxf(cm, __shfl_xor_sync(0xffffffffu, cm, off));
            float mn = fmaxf(m_i[i], cm);
            float f = __expf(m_i[i] - mn);
            float rs = 0.f;
#pragma unroll
            for (int j = 0; j < 4; j++) {
                float p = __expf(s[i][j] - mn);
                s[i][j] = p;
                rs += p;
            }
#pragma unroll
            for (int off = 8; off; off >>= 1)
                rs += __shfl_xor_sync(0xffffffffu, rs, off);
            l_i[i] = l_i[i] * f + rs;
            m_i[i] = mn;
#pragma unroll
            for (int j = 0; j < 4; j++) o[i][j] *= f;
            *(float4*)&Ps[(8 * ty + i) * PSP + 4 * tx] =
                make_float4(s[i][0], s[i][1], s[i][2], s[i][3]);
        }
        __syncthreads();

#pragma unroll 4
        for (int cc = 0; cc < KT; cc++) {
            float4 b4 = *(float4*)&Vs[cc * Dd + 4 * tx];
            float bf[4] = {b4.x, b4.y, b4.z, b4.w};
            float a[8];
#pragma unroll
            for (int i = 0; i < 8; i++) a[i] = Ps[(8 * ty + i) * PSP + cc];
#pragma unroll
            for (int i = 0; i < 8; i++)
#pragma unroll
                for (int j = 0; j < 4; j++) o[i][j] = fmaf(a[i], bf[j], o[i][j]);
        }
    }

#pragma unroll
    for (int i = 0; i < 8; i++) {
        int r = 8 * ty + i;
        if (r >= NQ) continue;
        float inv = 1.0f / l_i[i];
        float4 v4 = make_float4(o[i][0] * inv, o[i][1] * inv,
                                o[i][2] * inv, o[i][3] * inv);
        *(float4*)&g_ao[((long)(b * Nn + n0 + r)) * Cc + h * Dd + 4 * tx] = v4;
    }
}

// ---------------------------------------------------------------------------
extern "C" void kernel_launch(void* const* d_in, const int* in_sizes, int n_in,
                              void* d_out, int out_size)
{
    const float* x      = (const float*)d_in[0];
    const float* aw     = (const float*)d_in[1];
    const float* w_qkv  = (const float*)d_in[2];
    const float* b_qkv  = (const float*)d_in[3];
    const float* w_proj = (const float*)d_in[4];
    const float* b_proj = (const float*)d_in[5];

    float* out   = (float*)d_out;
    float* patch = out + (long)Bb * Nn * Cc;   // patch_attn after main output

    // attn needs >48KB dynamic smem: opt in every call (no static guards).
    const int smem_attn = (Dd * QT + Dd * KT + KT * Dd + QT * PSP) * (int)sizeof(float);
    cudaFuncSetAttribute(attn_flash, cudaFuncAttributeMaxDynamicSharedMemorySize, smem_attn);

    dim3 gq(QKVN / 128, (MM + 127) / 128);     // 18 x 73
    gemm_bf16s<0><<<gq, 256, GEMM_SMEM>>>(x, w_qkv, b_qkv, nullptr, QKVN);

    dim3 ga(NQT, Bb * Hh);                     // 5 x 192
    attn_flash<<<ga, 256, smem_attn>>>(aw, patch);

    dim3 gp(Cc / 128, (MM + 127) / 128);       // 6 x 73
    gemm_bf16s<1><<<gp, 256, GEMM_SMEM>>>(nullptr, w_proj, b_proj, out, Cc);
}

// round 11
// speedup vs baseline: 7.4786x; 1.3780x over previous
#include <cuda_runtime.h>
#include <cuda_bf16.h>
#include <cstdint>

// Problem constants
#define Bb 16
#define Nn 577
#define Cc 768
#define Hh 12
#define Dd 64
#define SCALEF 0.125f
#define ALPHAF 0.1f
#define MM (Bb * Nn)        // 9232 rows
#define QKVN (3 * Cc)       // 2304
#define KDIM 768
#define NPATCH (Nn - 1)     // 576

// Scratch (device globals; referenced ONLY from device code — GB300 ATS
// silently dereferences host shadows if passed as kernel args from host).
__device__ float g_q [Bb * Hh * Nn * Dd];   // [bh][n][d]
__device__ float g_k [Bb * Hh * Nn * Dd];   // [bh][n][d]
__device__ float g_v [Bb * Hh * Nn * Dd];   // [bh][n][d]
__device__ float g_ao[Bb * Nn * Cc];

// ===========================================================================
// Shared helpers: bf16 split-precision mma.m16n8k16
// ===========================================================================
__device__ __forceinline__ uint32_t smem_u32(const void* p) {
    return (uint32_t)__cvta_generic_to_shared(p);
}
__device__ __forceinline__ void ldsm4(uint32_t r[4], uint32_t addr) {
    asm volatile("ldmatrix.sync.aligned.m8n8.x4.shared.b16 {%0,%1,%2,%3}, [%4];"
        : "=r"(r[0]), "=r"(r[1]), "=r"(r[2]), "=r"(r[3]) : "r"(addr));
}
__device__ __forceinline__ void ldsm4t(uint32_t r[4], uint32_t addr) {
    asm volatile("ldmatrix.sync.aligned.m8n8.x4.trans.shared.b16 {%0,%1,%2,%3}, [%4];"
        : "=r"(r[0]), "=r"(r[1]), "=r"(r[2]), "=r"(r[3]) : "r"(addr));
}
__device__ __forceinline__ void mma16816(float c[4], const uint32_t a[4],
                                         uint32_t b0, uint32_t b1) {
    asm volatile(
        "mma.sync.aligned.m16n8k16.row.col.f32.bf16.bf16.f32 "
        "{%0,%1,%2,%3}, {%4,%5,%6,%7}, {%8,%9}, {%0,%1,%2,%3};"
        : "+f"(c[0]), "+f"(c[1]), "+f"(c[2]), "+f"(c[3])
        : "r"(a[0]), "r"(a[1]), "r"(a[2]), "r"(a[3]), "r"(b0), "r"(b1));
}
__device__ __forceinline__ uint32_t pack_hi(float x, float y,
                                            float& lx, float& ly) {
    __nv_bfloat16 hx = __float2bfloat16(x);
    __nv_bfloat16 hy = __float2bfloat16(y);
    lx = x - __bfloat162float(hx);
    ly = y - __bfloat162float(hy);
    __nv_bfloat162 p{hx, hy};
    return *(uint32_t*)&p;
}
__device__ __forceinline__ uint32_t pack_bf2(float x, float y) {
    __nv_bfloat162 p{__float2bfloat16(x), __float2bfloat16(y)};
    return *(uint32_t*)&p;
}

extern __shared__ unsigned char dynsm[];

// ===========================================================================
// bf16 split-precision GEMM (unchanged core from R10; epilogue layouts [bh][n][d])
// ===========================================================================
#define APITCH 40
#define BPITCH 136
#define STAGE_ELEMS (128 * APITCH * 2 + 32 * BPITCH * 2)
#define GEMM_SMEM (STAGE_ELEMS * 2)   // 37888 bytes

template <int EPI>
__global__ __launch_bounds__(256) void gemm_bf16s(
    const float* __restrict__ Ain,  // EPI==0: x
    const float* __restrict__ Bg,
    const float* __restrict__ bias,
    float* __restrict__ out,        // EPI==1 only
    int ldb)
{
    const float* __restrict__ A = (EPI == 1) ? (const float*)g_ao : Ain;

    __nv_bfloat16* sm = (__nv_bfloat16*)dynsm;
    const int tid  = threadIdx.x;
    const int lane = tid & 31, warp = tid >> 5;
    const int rowBase = blockIdx.y * 128;
    const int colBase = blockIdx.x * 128;
    const int wm0 = (warp >> 2) * 64;
    const int wn0 = (warp & 3) * 32;

    __nv_bfloat16* Ahi = sm;
    __nv_bfloat16* Alo = sm + 128 * APITCH;
    __nv_bfloat16* Bhi = sm + 256 * APITCH;
    __nv_bfloat16* Blo = sm + 256 * APITCH + 32 * BPITCH;

    const int aRow = tid >> 3;
    const int aK4  = (tid & 7) * 4;
    const int bK   = tid >> 5;
    const int bN4  = (tid & 31) * 4;

    float4 ar[4], br[4];
    auto do_load = [&](int k0) {
#pragma unroll
        for (int p = 0; p < 4; p++) {
            int gr = rowBase + aRow + 32 * p;
            ar[p] = (gr < MM) ? *(const float4*)(A + (long)gr * KDIM + k0 + aK4)
                              : make_float4(0.f, 0.f, 0.f, 0.f);
        }
#pragma unroll
        for (int p = 0; p < 4; p++)
            br[p] = *(const float4*)(Bg + (long)(k0 + bK + 8 * p) * ldb + colBase + bN4);
    };
    auto do_sts = [&]() {
#pragma unroll
        for (int p = 0; p < 4; p++) {
            int base = (aRow + 32 * p) * APITCH + aK4;
            float lx, ly, lz, lw;
            uint32_t h01 = pack_hi(ar[p].x, ar[p].y, lx, ly);
            uint32_t h23 = pack_hi(ar[p].z, ar[p].w, lz, lw);
            *(uint2*)&Ahi[base] = make_uint2(h01, h23);
            *(uint2*)&Alo[base] = make_uint2(pack_bf2(lx, ly), pack_bf2(lz, lw));
        }
#pragma unroll
        for (int p = 0; p < 4; p++) {
            int base = (bK + 8 * p) * BPITCH + bN4;
            float lx, ly, lz, lw;
            uint32_t h01 = pack_hi(br[p].x, br[p].y, lx, ly);
            uint32_t h23 = pack_hi(br[p].z, br[p].w, lz, lw);
            *(uint2*)&Bhi[base] = make_uint2(h01, h23);
            *(uint2*)&Blo[base] = make_uint2(pack_bf2(lx, ly), pack_bf2(lz, lw));
        }
    };

    float acc[4][4][4];
#pragma unroll
    for (int mi = 0; mi < 4; mi++)
#pragma unroll
        for (int j = 0; j < 4; j++)
#pragma unroll
            for (int r = 0; r < 4; r++) acc[mi][j][r] = 0.f;

    const int aOff = (wm0 + (lane & 15)) * (APITCH * 2) + (lane >> 4) * 16;
    const int bOff = (lane & 15) * (BPITCH * 2) + (wn0 + ((lane >> 4) << 3)) * 2;
    const uint32_t aHiB = smem_u32(Ahi) + aOff;
    const uint32_t aLoB = smem_u32(Alo) + aOff;
    const uint32_t bHiB = smem_u32(Bhi) + bOff;
    const uint32_t bLoB = smem_u32(Blo) + bOff;

    do_load(0);

#pragma unroll 1
    for (int t = 0; t < KDIM / 32; t++) {
        __syncthreads();
        do_sts();
        __syncthreads();
        if (t + 1 < KDIM / 32) do_load((t + 1) * 32);

#pragma unroll
        for (int ks = 0; ks < 2; ks++) {
            uint32_t ah[4][4], al[4][4], bh[2][4], bl[2][4];
#pragma unroll
            for (int mi = 0; mi < 4; mi++) {
                ldsm4(ah[mi], aHiB + mi * (16 * APITCH * 2) + ks * 32);
                ldsm4(al[mi], aLoB + mi * (16 * APITCH * 2) + ks * 32);
            }
#pragma unroll
            for (int nb = 0; nb < 2; nb++) {
                ldsm4t(bh[nb], bHiB + nb * 32 + ks * (16 * BPITCH * 2));
                ldsm4t(bl[nb], bLoB + nb * 32 + ks * (16 * BPITCH * 2));
            }
#pragma unroll
            for (int mi = 0; mi < 4; mi++)
#pragma unroll
                for (int j = 0; j < 4; j++) {
                    const int nb = j >> 1, hf = (j & 1) * 2;
                    mma16816(acc[mi][j], ah[mi], bh[nb][hf], bh[nb][hf + 1]);
                    mma16816(acc[mi][j], ah[mi], bl[nb][hf], bl[nb][hf + 1]);
                    mma16816(acc[mi][j], al[mi], bh[nb][hf], bh[nb][hf + 1]);
                }
        }
    }

#pragma unroll
    for (int mi = 0; mi < 4; mi++) {
        const int r0 = wm0 + mi * 16 + (lane >> 2);
#pragma unroll
        for (int half = 0; half < 2; half++) {
            const int gr = rowBase + r0 + half * 8;
            if (gr >= MM) continue;
            if (EPI == 0) {
                const int bidx = gr / Nn, n = gr % Nn;
#pragma unroll
                for (int j = 0; j < 4; j++) {
                    const int c0 = wn0 + j * 8 + (lane & 3) * 2;
#pragma unroll
                    for (int e = 0; e < 2; e++) {
                        const int gc = colBase + c0 + e;
                        float v = acc[mi][j][half * 2 + e] + bias[gc];
                        const int which = gc / Cc;
                        const int cc = gc % Cc;
                        const int h = cc >> 6, d = cc & 63;
                        const long base = (((long)bidx * Hh + h) * Nn + n) * Dd + d;
                        if (which == 0)      g_q[base] = v;
                        else if (which == 1) g_k[base] = v;
                        else                 g_v[base] = v;
                    }
                }
            } else {
#pragma unroll
                for (int j = 0; j < 4; j++) {
                    const int c0 = wn0 + j * 8 + (lane & 3) * 2;
                    const int gc = colBase + c0;
                    float2 v2 = make_float2(acc[mi][j][half * 2 + 0] + bias[gc],
                                            acc[mi][j][half * 2 + 1] + bias[gc + 1]);
                    *(float2*)&out[(long)gr * Cc + gc] = v2;
                }
            }
        }
    }
}

// ===========================================================================
// Tensor-core flash attention. Block = 128 q-rows of one (b,h), 256 thr.
// Warp w owns rows 16w..16w+15; per chunk (64 keys):
//   S = Q·K^T via split-bf16 mma (K b-frags via plain ldsm4: K is [c][d]),
//   online softmax on the C-fragments (4-lane shuffles),
//   O += P·V with P repacked in-register (C-frag layout == A-frag layout).
// Smem: Q(hi/lo) region aliased with K/V(hi/lo) region: 36,864 B (<48KB).
// ===========================================================================
#define QT 128
#define KT 64
#define NQT ((Nn + QT - 1) / QT)   // 5
#define NKT ((Nn + KT - 1) / KT)   // 10
#define QP 72                      // smem pitch in bf16 (144B: conflict-free ldsm)
#define ATTN_SMEM (2 * QT * QP * 2)   // 36864 bytes (Q region == K+V region)

__global__ __launch_bounds__(256) void attn_mma(
    const float* __restrict__ aw,   // [B, 576]
    float* __restrict__ patch)      // [B*H, 576]
{
    __nv_bfloat16* sm = (__nv_bfloat16*)dynsm;
    // Q region (prologue only)
    __nv_bfloat16* Qhi = sm;
    __nv_bfloat16* Qlo = sm + QT * QP;
    // K/V region (aliases Q region after Q frags are in registers)
    __nv_bfloat16* Khi = sm;
    __nv_bfloat16* Klo = sm + KT * QP;
    __nv_bfloat16* Vhi = sm + 2 * KT * QP;
    __nv_bfloat16* Vlo = sm + 3 * KT * QP;

    const int bh = blockIdx.y;
    const int b  = bh / Hh;
    const int h  = bh % Hh;
    const int qt = blockIdx.x;
    const int n0 = qt * QT;
    const int NQ = min(QT, Nn - n0);

    const int tid  = threadIdx.x;
    const int lane = tid & 31, warp = tid >> 5;

    // ---- stage Q tile into smem as bf16 hi/lo ----
    {
        const int r = tid >> 1;                 // 0..127
        const int d0 = (tid & 1) * 32;          // 0 or 32
        const float* src = g_q + ((long)bh * Nn + n0 + r) * Dd + d0;
        const bool valid = (r < NQ);
#pragma unroll
        for (int i = 0; i < 8; i++) {
            float4 f = valid ? *(const float4*)(src + 4 * i)
                             : make_float4(0.f, 0.f, 0.f, 0.f);
            float lx, ly, lz, lw;
            uint32_t h01 = pack_hi(f.x, f.y, lx, ly);
            uint32_t h23 = pack_hi(f.z, f.w, lz, lw);
            int base = r * QP + d0 + 4 * i;
            *(uint2*)&Qhi[base] = make_uint2(h01, h23);
            *(uint2*)&Qlo[base] = make_uint2(pack_bf2(lx, ly), pack_bf2(lz, lw));
        }
    }
    __syncthreads();

    // ---- Q fragments to registers (A-operand, rows warp*16 + (lane&15)) ----
    uint32_t qh[4][4], ql[4][4];
    {
        const uint32_t qLane = ((warp << 4) + (lane & 15)) * (QP * 2) + (lane >> 4) * 16;
        const uint32_t QhiB = smem_u32(Qhi) + qLane;
        const uint32_t QloB = smem_u32(Qlo) + qLane;
#pragma unroll
        for (int ks = 0; ks < 4; ks++) {
            ldsm4(qh[ks], QhiB + ks * 32);
            ldsm4(ql[ks], QloB + ks * 32);
        }
    }
    __syncthreads();   // Q smem reads done; K/V may overwrite

    // softmax state: rows rlo = warp*16 + lane/4, rhi = +8
    float m_lo = -1e30f, m_hi = -1e30f, l_lo = 0.f, l_hi = 0.f;
    float o[8][4];
#pragma unroll
    for (int nt = 0; nt < 8; nt++)
#pragma unroll
        for (int e = 0; e < 4; e++) o[nt][e] = 0.f;

    const uint32_t fragLane = (lane & 15) * (QP * 2) + (lane >> 4) * 16;
    const uint32_t KhiB = smem_u32(Khi) + fragLane;
    const uint32_t KloB = smem_u32(Klo) + fragLane;
    const uint32_t VhiB = smem_u32(Vhi) + fragLane;
    const uint32_t VloB = smem_u32(Vlo) + fragLane;
    const int cbase = 2 * (lane & 3);
    const bool clsLane = (qt == 0) && (warp == 0) && ((lane >> 2) == 0);

#pragma unroll 1
    for (int ch = 0; ch < NKT; ch++) {
        const int kc0 = ch * KT;
        const int KC  = min(KT, Nn - kc0);

        // ---- load K and V chunk (fp32 -> bf16 hi/lo) ----
        {
            const int c  = tid >> 2;            // 0..63
            const int d0 = (tid & 3) * 16;      // 0,16,32,48
            const bool valid = (kc0 + c < Nn);
            const long gbase = ((long)bh * Nn + kc0 + c) * Dd + d0;
#pragma unroll
            for (int i = 0; i < 4; i++) {
                float4 f = valid ? *(const float4*)(g_k + gbase + 4 * i)
                                 : make_float4(0.f, 0.f, 0.f, 0.f);
                float lx, ly, lz, lw;
                uint32_t h01 = pack_hi(f.x, f.y, lx, ly);
                uint32_t h23 = pack_hi(f.z, f.w, lz, lw);
                int base = c * QP + d0 + 4 * i;
                *(uint2*)&Khi[base] = make_uint2(h01, h23);
                *(uint2*)&Klo[base] = make_uint2(pack_bf2(lx, ly), pack_bf2(lz, lw));
            }
#pragma unroll
            for (int i = 0; i < 4; i++) {
                float4 f = valid ? *(const float4*)(g_v + gbase + 4 * i)
                                 : make_float4(0.f, 0.f, 0.f, 0.f);
                float lx, ly, lz, lw;
                uint32_t h01 = pack_hi(f.x, f.y, lx, ly);
                uint32_t h23 = pack_hi(f.z, f.w, lz, lw);
                int base = c * QP + d0 + 4 * i;
                *(uint2*)&Vhi[base] = make_uint2(h01, h23);
                *(uint2*)&Vlo[base] = make_uint2(pack_bf2(lx, ly), pack_bf2(lz, lw));
            }
        }
        __syncthreads();

        // ---- S = Q·K^T (split bf16, 3 products) ----
        float s[8][4];
#pragma unroll
        for (int nt = 0; nt < 8; nt++)
#pragma unroll
            for (int e = 0; e < 4; e++) s[nt][e] = 0.f;

#pragma unroll
        for (int ks = 0; ks < 4; ks++)
#pragma unroll
            for (int g = 0; g < 4; g++) {
                uint32_t kh[4], kl[4];
                const uint32_t off = g * (16 * QP * 2) + ks * 32;
                ldsm4(kh, KhiB + off);
                ldsm4(kl, KloB + off);
                // non-trans x4 at rows n: ntile 2g -> regs {0,2}, 2g+1 -> {1,3}
                mma16816(s[2 * g],     qh[ks], kh[0], kh[2]);
                mma16816(s[2 * g],     qh[ks], kl[0], kl[2]);
                mma16816(s[2 * g],     ql[ks], kh[0], kh[2]);
                mma16816(s[2 * g + 1], qh[ks], kh[1], kh[3]);
                mma16816(s[2 * g + 1], qh[ks], kl[1], kl[3]);
                mma16816(s[2 * g + 1], ql[ks], kh[1], kh[3]);
            }

        // ---- scale + mask ----
#pragma unroll
        for (int nt = 0; nt < 8; nt++)
#pragma unroll
            for (int e = 0; e < 4; e++) {
                const int c = nt * 8 + cbase + (e & 1);
                float sv = s[nt][e] * SCALEF;
                s[nt][e] = (c < KC) ? sv : -1e30f;
            }

        // ---- CLS row: emit pre-reweight patch scores, apply reweight ----
        if (clsLane) {
            // global row 0 = rlo of this lane; regs e = 0,1
#pragma unroll
            for (int nt = 0; nt < 8; nt++)
#pragma unroll
                for (int e = 0; e < 2; e++) {
                    const int mg = kc0 + nt * 8 + cbase + e;
                    if (mg >= 1 && mg < Nn) {
                        const float sv = s[nt][e];
                        patch[(long)bh * NPATCH + mg - 1] = sv;
                        const float w = aw[(long)b * NPATCH + mg - 1];
                        s[nt][e] = sv * (w * ALPHAF + (1.0f - ALPHAF));
                    }
                }
        }

        // ---- online softmax (rows rlo: regs 0,1 / rhi: regs 2,3) ----
        {
            float cmlo = -1e30f, cmhi = -1e30f;
#pragma unroll
            for (int nt = 0; nt < 8; nt++) {
                cmlo = fmaxf(cmlo, fmaxf(s[nt][0], s[nt][1]));
                cmhi = fmaxf(cmhi, fmaxf(s[nt][2], s[nt][3]));
            }
#pragma unroll
            for (int off = 1; off <= 2; off <<= 1) {
                cmlo = fmaxf(cmlo, __shfl_xor_sync(0xffffffffu, cmlo, off));
                cmhi = fmaxf(cmhi, __shfl_xor_sync(0xffffffffu, cmhi, off));
            }
            const float mnlo = fmaxf(m_lo, cmlo);
            const float mnhi = fmaxf(m_hi, cmhi);
            const float flo = __expf(m_lo - mnlo);
            const float fhi = __expf(m_hi - mnhi);
            float rslo = 0.f, rshi = 0.f;
#pragma unroll
            for (int nt = 0; nt < 8; nt++) {
                s[nt][0] = __expf(s[nt][0] - mnlo); rslo += s[nt][0];
                s[nt][1] = __expf(s[nt][1] - mnlo); rslo += s[nt][1];
                s[nt][2] = __expf(s[nt][2] - mnhi); rshi += s[nt][2];
                s[nt][3] = __expf(s[nt][3] - mnhi); rshi += s[nt][3];
            }
#pragma unroll
            for (int off = 1; off <= 2; off <<= 1) {
                rslo += __shfl_xor_sync(0xffffffffu, rslo, off);
                rshi += __shfl_xor_sync(0xffffffffu, rshi, off);
            }
            l_lo = l_lo * flo + rslo;  m_lo = mnlo;
            l_hi = l_hi * fhi + rshi;  m_hi = mnhi;
#pragma unroll
            for (int nt = 0; nt < 8; nt++) {
                o[nt][0] *= flo; o[nt][1] *= flo;
                o[nt][2] *= fhi; o[nt][3] *= fhi;
            }
        }

        // ---- O += P·V  (P repacked in-register: C-frag layout == A-frag) ----
#pragma unroll
        for (int kt = 0; kt < 4; kt++) {
            uint32_t pa_h[4], pa_l[4];
            {
                float lx, ly;
                pa_h[0] = pack_hi(s[2 * kt][0],     s[2 * kt][1],     lx, ly);
                pa_l[0] = pack_bf2(lx, ly);
                pa_h[1] = pack_hi(s[2 * kt][2],     s[2 * kt][3],     lx, ly);
                pa_l[1] = pack_bf2(lx, ly);
                pa_h[2] = pack_hi(s[2 * kt + 1][0], s[2 * kt + 1][1], lx, ly);
                pa_l[2] = pack_bf2(lx, ly);
                pa_h[3] = pack_hi(s[2 * kt + 1][2], s[2 * kt + 1][3], lx, ly);
                pa_l[3] = pack_bf2(lx, ly);
            }
#pragma unroll
            for (int g = 0; g < 4; g++) {
                uint32_t vh[4], vl[4];
                const uint32_t off = kt * (16 * QP * 2) + g * 32;
                ldsm4t(vh, VhiB + off);
                ldsm4t(vl, VloB + off);
                // trans x4: ntile 2g -> regs {0,1}, 2g+1 -> {2,3}
                mma16816(o[2 * g],     pa_h, vh[0], vh[1]);
                mma16816(o[2 * g],     pa_h, vl[0], vl[1]);
                mma16816(o[2 * g],     pa_l, vh[0], vh[1]);
                mma16816(o[2 * g + 1], pa_h, vh[2], vh[3]);
                mma16816(o[2 * g + 1], pa_h, vl[2], vl[3]);
                mma16816(o[2 * g + 1], pa_l, vh[2], vh[3]);
            }
        }
        __syncthreads();   // PV smem reads done before next chunk overwrite
    }

    // ---- write O (normalized) to g_ao[b*Nn+n][h*64+d] ----
    {
        const int rlo = warp * 16 + (lane >> 2);
        const float invlo = 1.0f / l_lo;
        const float invhi = 1.0f / l_hi;
#pragma unroll
        for (int nt = 0; nt < 8; nt++) {
            const int d = h * Dd + nt * 8 + cbase;
            if (rlo < NQ)
                *(float2*)&g_ao[((long)(b * Nn + n0 + rlo)) * Cc + d] =
                    make_float2(o[nt][0] * invlo, o[nt][1] * invlo);
            if (rlo + 8 < NQ)
                *(float2*)&g_ao[((long)(b * Nn + n0 + rlo + 8)) * Cc + d] =
                    make_float2(o[nt][2] * invhi, o[nt][3] * invhi);
        }
    }
}

// ---------------------------------------------------------------------------
extern "C" void kernel_launch(void* const* d_in, const int* in_sizes, int n_in,
                              void* d_out, int out_size)
{
    const float* x      = (const float*)d_in[0];
    const float* aw     = (const float*)d_in[1];
    const float* w_qkv  = (const float*)d_in[2];
    const float* b_qkv  = (const float*)d_in[3];
    const float* w_proj = (const float*)d_in[4];
    const float* b_proj = (const float*)d_in[5];

    float* out   = (float*)d_out;
    float* patch = out + (long)Bb * Nn * Cc;   // patch_attn after main output

    dim3 gq(QKVN / 128, (MM + 127) / 128);     // 18 x 73
    gemm_bf16s<0><<<gq, 256, GEMM_SMEM>>>(x, w_qkv, b_qkv, nullptr, QKVN);

    dim3 ga(NQT, Bb * Hh);                     // 5 x 192
    attn_mma<<<ga, 256, ATTN_SMEM>>>(aw, patch);

    dim3 gp(Cc / 128, (MM + 127) / 128);       // 6 x 73
    gemm_bf16s<1><<<gp, 256, GEMM_SMEM>>>(nullptr, w_proj, b_proj, out, Cc);
}

// round 12
// speedup vs baseline: 8.4337x; 1.1277x over previous
#include <cuda_runtime.h>
#include <cuda_bf16.h>
#include <cstdint>

// Problem constants
#define Bb 16
#define Nn 577
#define Cc 768
#define Hh 12
#define Dd 64
#define SCALEF 0.125f
#define ALPHAF 0.1f
#define MM (Bb * Nn)        // 9232
#define QKVN (3 * Cc)       // 2304
#define KDIM 768
#define NPATCH (Nn - 1)     // 576

#define NX  (MM * KDIM)     // 7,090,176
#define NWQ (KDIM * QKVN)   // 1,769,472
#define NWP (KDIM * Cc)     //   589,824

// Device-global scratch (referenced ONLY from device code — GB300 ATS
// silently dereferences host shadows passed as kernel args; R8/R9 bug).
// All operands pre-split into bf16 hi/lo pairs.
__device__ __nv_bfloat16 g_xh[NX],  g_xl[NX];
__device__ __nv_bfloat16 g_wqh[NWQ], g_wql[NWQ];
__device__ __nv_bfloat16 g_wph[NWP], g_wpl[NWP];
__device__ __nv_bfloat16 g_qh[Bb * Hh * Nn * Dd], g_ql[Bb * Hh * Nn * Dd];
__device__ __nv_bfloat16 g_kh[Bb * Hh * Nn * Dd], g_kl[Bb * Hh * Nn * Dd];
__device__ __nv_bfloat16 g_vh[Bb * Hh * Nn * Dd], g_vl[Bb * Hh * Nn * Dd];
__device__ __nv_bfloat16 g_aoh[MM * Cc], g_aol[MM * Cc];

// ===========================================================================
// Helpers
// ===========================================================================
__device__ __forceinline__ uint32_t smem_u32(const void* p) {
    return (uint32_t)__cvta_generic_to_shared(p);
}
__device__ __forceinline__ void ldsm4(uint32_t r[4], uint32_t addr) {
    asm volatile("ldmatrix.sync.aligned.m8n8.x4.shared.b16 {%0,%1,%2,%3}, [%4];"
        : "=r"(r[0]), "=r"(r[1]), "=r"(r[2]), "=r"(r[3]) : "r"(addr));
}
__device__ __forceinline__ void ldsm4t(uint32_t r[4], uint32_t addr) {
    asm volatile("ldmatrix.sync.aligned.m8n8.x4.trans.shared.b16 {%0,%1,%2,%3}, [%4];"
        : "=r"(r[0]), "=r"(r[1]), "=r"(r[2]), "=r"(r[3]) : "r"(addr));
}
__device__ __forceinline__ void mma16816(float c[4], const uint32_t a[4],
                                         uint32_t b0, uint32_t b1) {
    asm volatile(
        "mma.sync.aligned.m16n8k16.row.col.f32.bf16.bf16.f32 "
        "{%0,%1,%2,%3}, {%4,%5,%6,%7}, {%8,%9}, {%0,%1,%2,%3};"
        : "+f"(c[0]), "+f"(c[1]), "+f"(c[2]), "+f"(c[3])
        : "r"(a[0]), "r"(a[1]), "r"(a[2]), "r"(a[3]), "r"(b0), "r"(b1));
}
__device__ __forceinline__ uint32_t pack_hi(float x, float y,
                                            float& lx, float& ly) {
    __nv_bfloat16 hx = __float2bfloat16(x);
    __nv_bfloat16 hy = __float2bfloat16(y);
    lx = x - __bfloat162float(hx);
    ly = y - __bfloat162float(hy);
    __nv_bfloat162 p{hx, hy};
    return *(uint32_t*)&p;
}
__device__ __forceinline__ uint32_t pack_bf2(float x, float y) {
    __nv_bfloat162 p{__float2bfloat16(x), __float2bfloat16(y)};
    return *(uint32_t*)&p;
}
__device__ __forceinline__ void split1(float v, __nv_bfloat16& h, __nv_bfloat16& l) {
    h = __float2bfloat16(v);
    l = __float2bfloat16(v - __bfloat162float(h));
}
__device__ __forceinline__ void cp16(uint32_t dst, const void* src, bool pred) {
    int sz = pred ? 16 : 0;
    asm volatile("cp.async.cg.shared.global [%0], [%1], 16, %2;"
                 :: "r"(dst), "l"(src), "r"(sz));
}
__device__ __forceinline__ void cp_commit() {
    asm volatile("cp.async.commit_group;");
}
__device__ __forceinline__ void cp_wait1() {
    asm volatile("cp.async.wait_group 1;");
}

extern __shared__ unsigned char dynsm[];

// ===========================================================================
// Pre-split kernel: x, w_qkv, w_proj -> bf16 hi/lo device arrays
// ===========================================================================
__global__ __launch_bounds__(256) void split_all(
    const float* __restrict__ x,
    const float* __restrict__ wq,
    const float* __restrict__ wp)
{
    long i = ((long)blockIdx.x * 256 + threadIdx.x) * 4;
    const float* src;
    __nv_bfloat16 *dh, *dl;
    long o;
    if (i < NX)                 { src = x;  dh = g_xh;  dl = g_xl;  o = i; }
    else if (i < NX + NWQ)      { src = wq; dh = g_wqh; dl = g_wql; o = i - NX; }
    else if (i < NX + NWQ + NWP){ src = wp; dh = g_wph; dl = g_wpl; o = i - NX - NWQ; }
    else return;
    float4 f = *(const float4*)(src + o);
    __nv_bfloat16 h0, h1, h2, h3, l0, l1, l2, l3;
    split1(f.x, h0, l0); split1(f.y, h1, l1);
    split1(f.z, h2, l2); split1(f.w, h3, l3);
    __nv_bfloat162 ph0{h0, h1}, ph1{h2, h3}, pl0{l0, l1}, pl1{l2, l3};
    *(uint2*)(dh + o) = make_uint2(*(uint32_t*)&ph0, *(uint32_t*)&ph1);
    *(uint2*)(dl + o) = make_uint2(*(uint32_t*)&pl0, *(uint32_t*)&pl1);
}

// ===========================================================================
// Split-bf16 tensor GEMM, cp.async 3-stage pipeline. 128x128 tile, kt=32.
// A/B already hi/lo bf16 in gmem. Smem layout per stage identical to R11
// (proven ldmatrix addressing). EPI 0: x@w_qkv -> q/k/v hi/lo scatter.
// EPI 1: ao@w_proj -> out fp32 + bias.
// ===========================================================================
#define APITCH 40
#define BPITCH 136
#define STAGE_ELEMS (128 * APITCH * 2 + 32 * BPITCH * 2)   // 18944 bf16
#define STAGE_BYTES (STAGE_ELEMS * 2)                       // 37888
#define NSTAGE 3
#define GEMM_SMEM (NSTAGE * STAGE_BYTES)                    // 113664

template <int EPI>
__global__ __launch_bounds__(256) void gemm_pipe(
    const float* __restrict__ bias,
    float* __restrict__ out)        // EPI==1 only
{
    constexpr int LDB = EPI ? Cc : QKVN;
    constexpr int NT  = KDIM / 32;  // 24
    const __nv_bfloat16* Ah = EPI ? g_aoh : g_xh;
    const __nv_bfloat16* Al = EPI ? g_aol : g_xl;
    const __nv_bfloat16* Bh = EPI ? g_wph : g_wqh;
    const __nv_bfloat16* Bl = EPI ? g_wpl : g_wql;

    const int tid  = threadIdx.x;
    const int lane = tid & 31, warp = tid >> 5;
    const int rowBase = blockIdx.y * 128;
    const int colBase = blockIdx.x * 128;
    const int wm0 = (warp >> 2) * 64;
    const int wn0 = (warp & 3) * 32;
    const uint32_t smemBase = smem_u32(dynsm);

    auto issue_tile = [&](int tile, int stage) {
        const int k0 = tile * 32;
        const uint32_t sb = smemBase + stage * STAGE_BYTES;
#pragma unroll
        for (int rep = 0; rep < 2; rep++) {            // A: 512 granules
            const int g = tid + rep * 256;
            const int row = g >> 2, kc = g & 3;
            const int gr = rowBase + row;
            const bool ok = gr < MM;
            const long so = (long)(ok ? gr : 0) * KDIM + k0 + kc * 8;
            const uint32_t d = sb + (row * APITCH + kc * 8) * 2;
            cp16(d,                    Ah + so, ok);
            cp16(d + 128 * APITCH * 2, Al + so, ok);
        }
#pragma unroll
        for (int rep = 0; rep < 2; rep++) {            // B: 512 granules
            const int g = tid + rep * 256;
            const int krow = g >> 4, nc = g & 15;
            const long so = (long)(k0 + krow) * LDB + colBase + nc * 8;
            const uint32_t d = sb + (256 * APITCH + krow * BPITCH + nc * 8) * 2;
            cp16(d,                   Bh + so, true);
            cp16(d + 32 * BPITCH * 2, Bl + so, true);
        }
        cp_commit();
    };

    float acc[4][4][4];
#pragma unroll
    for (int mi = 0; mi < 4; mi++)
#pragma unroll
        for (int j = 0; j < 4; j++)
#pragma unroll
            for (int r = 0; r < 4; r++) acc[mi][j][r] = 0.f;

    const int aOff = (wm0 + (lane & 15)) * (APITCH * 2) + (lane >> 4) * 16;
    const int bOff = (lane & 15) * (BPITCH * 2) + (wn0 + ((lane >> 4) << 3)) * 2;

    issue_tile(0, 0);
    issue_tile(1, 1);

#pragma unroll 1
    for (int t = 0; t < NT; t++) {
        cp_wait1();
        __syncthreads();
        if (t + 2 < NT) issue_tile(t + 2, (t + 2) % NSTAGE);
        else cp_commit();   // keep group accounting uniform

        const uint32_t base = smemBase + (t % NSTAGE) * STAGE_BYTES;
        const uint32_t aHiB = base + aOff;
        const uint32_t aLoB = aHiB + 128 * APITCH * 2;
        const uint32_t bHiB = base + 256 * APITCH * 2 + bOff;
        const uint32_t bLoB = bHiB + 32 * BPITCH * 2;

#pragma unroll
        for (int ks = 0; ks < 2; ks++) {
            uint32_t ah[4][4], al[4][4], bh[2][4], bl[2][4];
#pragma unroll
            for (int mi = 0; mi < 4; mi++) {
                ldsm4(ah[mi], aHiB + mi * (16 * APITCH * 2) + ks * 32);
                ldsm4(al[mi], aLoB + mi * (16 * APITCH * 2) + ks * 32);
            }
#pragma unroll
            for (int nb = 0; nb < 2; nb++) {
                ldsm4t(bh[nb], bHiB + nb * 32 + ks * (16 * BPITCH * 2));
                ldsm4t(bl[nb], bLoB + nb * 32 + ks * (16 * BPITCH * 2));
            }
#pragma unroll
            for (int mi = 0; mi < 4; mi++)
#pragma unroll
                for (int j = 0; j < 4; j++) {
                    const int nb = j >> 1, hf = (j & 1) * 2;
                    mma16816(acc[mi][j], ah[mi], bh[nb][hf], bh[nb][hf + 1]);
                    mma16816(acc[mi][j], ah[mi], bl[nb][hf], bl[nb][hf + 1]);
                    mma16816(acc[mi][j], al[mi], bh[nb][hf], bh[nb][hf + 1]);
                }
        }
    }

    // ---- epilogue ----
#pragma unroll
    for (int mi = 0; mi < 4; mi++) {
        const int r0 = wm0 + mi * 16 + (lane >> 2);
#pragma unroll
        for (int half = 0; half < 2; half++) {
            const int gr = rowBase + r0 + half * 8;
            if (gr >= MM) continue;
            if (EPI == 0) {
                const int bidx = gr / Nn, n = gr % Nn;
#pragma unroll
                for (int j = 0; j < 4; j++) {
                    const int c0 = wn0 + j * 8 + (lane & 3) * 2;
#pragma unroll
                    for (int e = 0; e < 2; e++) {
                        const int gc = colBase + c0 + e;
                        float v = acc[mi][j][half * 2 + e] + bias[gc];
                        const int which = gc / Cc;
                        const int cc = gc % Cc;
                        const int h = cc >> 6, d = cc & 63;
                        const long base = (((long)bidx * Hh + h) * Nn + n) * Dd + d;
                        __nv_bfloat16 hh, ll;
                        split1(v, hh, ll);
                        if (which == 0)      { g_qh[base] = hh; g_ql[base] = ll; }
                        else if (which == 1) { g_kh[base] = hh; g_kl[base] = ll; }
                        else                 { g_vh[base] = hh; g_vl[base] = ll; }
                    }
                }
            } else {
#pragma unroll
                for (int j = 0; j < 4; j++) {
                    const int c0 = wn0 + j * 8 + (lane & 3) * 2;
                    const int gc = colBase + c0;
                    float2 v2 = make_float2(acc[mi][j][half * 2 + 0] + bias[gc],
                                            acc[mi][j][half * 2 + 1] + bias[gc + 1]);
                    *(float2*)&out[(long)gr * Cc + gc] = v2;
                }
            }
        }
    }
}

// ===========================================================================
// Tensor-core flash attention (R11-proven MMA logic; staging now copies
// pre-split bf16 hi/lo — no in-loop conversion). 128 q-rows/block, 256 thr.
// ===========================================================================
#define QT 128
#define KT 64
#define NQT ((Nn + QT - 1) / QT)   // 5
#define NKT ((Nn + KT - 1) / KT)   // 10
#define QP 72                      // smem pitch in bf16 (144B, conflict-free)
#define ATTN_SMEM (2 * QT * QP * 2)   // 36864 bytes

__global__ __launch_bounds__(256) void attn_mma(
    const float* __restrict__ aw,   // [B, 576]
    float* __restrict__ patch)      // [B*H, 576]
{
    __nv_bfloat16* sm = (__nv_bfloat16*)dynsm;
    __nv_bfloat16* Qhi = sm;                  // prologue only
    __nv_bfloat16* Qlo = sm + QT * QP;
    __nv_bfloat16* Khi = sm;                  // aliases Q region
    __nv_bfloat16* Klo = sm + KT * QP;
    __nv_bfloat16* Vhi = sm + 2 * KT * QP;
    __nv_bfloat16* Vlo = sm + 3 * KT * QP;

    const int bh = blockIdx.y;
    const int b  = bh / Hh;
    const int h  = bh % Hh;
    const int qt = blockIdx.x;
    const int n0 = qt * QT;
    const int NQ = min(QT, Nn - n0);

    const int tid  = threadIdx.x;
    const int lane = tid & 31, warp = tid >> 5;

    // ---- stage Q tile (hi/lo bf16 straight copy) ----
    {
        const int r = tid >> 1;
        const int half = tid & 1;            // 4 uint4 each
        const bool valid = (r < NQ);
        const long gb = ((long)bh * Nn + n0 + (valid ? r : 0)) * Dd;
        const uint4* sh = (const uint4*)(g_qh + gb) + half * 4;
        const uint4* sl = (const uint4*)(g_ql + gb) + half * 4;
        uint4* dh = (uint4*)(Qhi + r * QP + half * 32);
        uint4* dl = (uint4*)(Qlo + r * QP + half * 32);
        const uint4 z = make_uint4(0, 0, 0, 0);
#pragma unroll
        for (int i = 0; i < 4; i++) {
            dh[i] = valid ? sh[i] : z;
            dl[i] = valid ? sl[i] : z;
        }
    }
    __syncthreads();

    // ---- Q fragments to registers ----
    uint32_t qh[4][4], ql[4][4];
    {
        const uint32_t qLane = ((warp << 4) + (lane & 15)) * (QP * 2) + (lane >> 4) * 16;
        const uint32_t QhiB = smem_u32(Qhi) + qLane;
        const uint32_t QloB = smem_u32(Qlo) + qLane;
#pragma unroll
        for (int ks = 0; ks < 4; ks++) {
            ldsm4(qh[ks], QhiB + ks * 32);
            ldsm4(ql[ks], QloB + ks * 32);
        }
    }
    __syncthreads();

    float m_lo = -1e30f, m_hi = -1e30f, l_lo = 0.f, l_hi = 0.f;
    float o[8][4];
#pragma unroll
    for (int nt = 0; nt < 8; nt++)
#pragma unroll
        for (int e = 0; e < 4; e++) o[nt][e] = 0.f;

    const uint32_t fragLane = (lane & 15) * (QP * 2) + (lane >> 4) * 16;
    const uint32_t KhiB = smem_u32(Khi) + fragLane;
    const uint32_t KloB = smem_u32(Klo) + fragLane;
    const uint32_t VhiB = smem_u32(Vhi) + fragLane;
    const uint32_t VloB = smem_u32(Vlo) + fragLane;
    const int cbase = 2 * (lane & 3);
    const bool clsLane = (qt == 0) && (warp == 0) && ((lane >> 2) == 0);

#pragma unroll 1
    for (int ch = 0; ch < NKT; ch++) {
        const int kc0 = ch * KT;
        const int KC  = min(KT, Nn - kc0);

        // ---- stage K and V chunk (straight hi/lo copies) ----
        {
            const int c  = tid >> 2;
            const int q4 = tid & 3;          // 2 uint4 each per array
            const bool valid = (kc0 + c < Nn);
            const long gb = ((long)bh * Nn + kc0 + (valid ? c : 0)) * Dd;
            const int so = q4 * 2;           // uint4 index
            const int de = c * QP + q4 * 16; // elem offset
            const uint4 z = make_uint4(0, 0, 0, 0);
#pragma unroll
            for (int i = 0; i < 2; i++) {
                ((uint4*)(Khi + de))[i] = valid ? ((const uint4*)(g_kh + gb))[so + i] : z;
                ((uint4*)(Klo + de))[i] = valid ? ((const uint4*)(g_kl + gb))[so + i] : z;
                ((uint4*)(Vhi + de))[i] = valid ? ((const uint4*)(g_vh + gb))[so + i] : z;
                ((uint4*)(Vlo + de))[i] = valid ? ((const uint4*)(g_vl + gb))[so + i] : z;
            }
        }
        __syncthreads();

        // ---- S = Q·K^T ----
        float s[8][4];
#pragma unroll
        for (int nt = 0; nt < 8; nt++)
#pragma unroll
            for (int e = 0; e < 4; e++) s[nt][e] = 0.f;

#pragma unroll
        for (int ks = 0; ks < 4; ks++)
#pragma unroll
            for (int g = 0; g < 4; g++) {
                uint32_t kh[4], kl[4];
                const uint32_t off = g * (16 * QP * 2) + ks * 32;
                ldsm4(kh, KhiB + off);
                ldsm4(kl, KloB + off);
                mma16816(s[2 * g],     qh[ks], kh[0], kh[2]);
                mma16816(s[2 * g],     qh[ks], kl[0], kl[2]);
                mma16816(s[2 * g],     ql[ks], kh[0], kh[2]);
                mma16816(s[2 * g + 1], qh[ks], kh[1], kh[3]);
                mma16816(s[2 * g + 1], qh[ks], kl[1], kl[3]);
                mma16816(s[2 * g + 1], ql[ks], kh[1], kh[3]);
            }

        // ---- scale + mask ----
#pragma unroll
        for (int nt = 0; nt < 8; nt++)
#pragma unroll
            for (int e = 0; e < 4; e++) {
                const int c = nt * 8 + cbase + (e & 1);
                float sv = s[nt][e] * SCALEF;
                s[nt][e] = (c < KC) ? sv : -1e30f;
            }

        // ---- CLS row ----
        if (clsLane) {
#pragma unroll
            for (int nt = 0; nt < 8; nt++)
#pragma unroll
                for (int e = 0; e < 2; e++) {
                    const int mg = kc0 + nt * 8 + cbase + e;
                    if (mg >= 1 && mg < Nn) {
                        const float sv = s[nt][e];
                        patch[(long)bh * NPATCH + mg - 1] = sv;
                        const float w = aw[(long)b * NPATCH + mg - 1];
                        s[nt][e] = sv * (w * ALPHAF + (1.0f - ALPHAF));
                    }
                }
        }

        // ---- online softmax ----
        {
            float cmlo = -1e30f, cmhi = -1e30f;
#pragma unroll
            for (int nt = 0; nt < 8; nt++) {
                cmlo = fmaxf(cmlo, fmaxf(s[nt][0], s[nt][1]));
                cmhi = fmaxf(cmhi, fmaxf(s[nt][2], s[nt][3]));
            }
#pragma unroll
            for (int off = 1; off <= 2; off <<= 1) {
                cmlo = fmaxf(cmlo, __shfl_xor_sync(0xffffffffu, cmlo, off));
                cmhi = fmaxf(cmhi, __shfl_xor_sync(0xffffffffu, cmhi, off));
            }
            const float mnlo = fmaxf(m_lo, cmlo);
            const float mnhi = fmaxf(m_hi, cmhi);
            const float flo = __expf(m_lo - mnlo);
            const float fhi = __expf(m_hi - mnhi);
            float rslo = 0.f, rshi = 0.f;
#pragma unroll
            for (int nt = 0; nt < 8; nt++) {
                s[nt][0] = __expf(s[nt][0] - mnlo); rslo += s[nt][0];
                s[nt][1] = __expf(s[nt][1] - mnlo); rslo += s[nt][1];
                s[nt][2] = __expf(s[nt][2] - mnhi); rshi += s[nt][2];
                s[nt][3] = __expf(s[nt][3] - mnhi); rshi += s[nt][3];
            }
#pragma unroll
            for (int off = 1; off <= 2; off <<= 1) {
                rslo += __shfl_xor_sync(0xffffffffu, rslo, off);
                rshi += __shfl_xor_sync(0xffffffffu, rshi, off);
            }
            l_lo = l_lo * flo + rslo;  m_lo = mnlo;
            l_hi = l_hi * fhi + rshi;  m_hi = mnhi;
#pragma unroll
            for (int nt = 0; nt < 8; nt++) {
                o[nt][0] *= flo; o[nt][1] *= flo;
                o[nt][2] *= fhi; o[nt][3] *= fhi;
            }
        }

        // ---- O += P·V ----
#pragma unroll
        for (int kt = 0; kt < 4; kt++) {
            uint32_t pa_h[4], pa_l[4];
            {
                float lx, ly;
                pa_h[0] = pack_hi(s[2 * kt][0],     s[2 * kt][1],     lx, ly);
                pa_l[0] = pack_bf2(lx, ly);
                pa_h[1] = pack_hi(s[2 * kt][2],     s[2 * kt][3],     lx, ly);
                pa_l[1] = pack_bf2(lx, ly);
                pa_h[2] = pack_hi(s[2 * kt + 1][0], s[2 * kt + 1][1], lx, ly);
                pa_l[2] = pack_bf2(lx, ly);
                pa_h[3] = pack_hi(s[2 * kt + 1][2], s[2 * kt + 1][3], lx, ly);
                pa_l[3] = pack_bf2(lx, ly);
            }
#pragma unroll
            for (int g = 0; g < 4; g++) {
                uint32_t vh[4], vl[4];
                const uint32_t off = kt * (16 * QP * 2) + g * 32;
                ldsm4t(vh, VhiB + off);
                ldsm4t(vl, VloB + off);
                mma16816(o[2 * g],     pa_h, vh[0], vh[1]);
                mma16816(o[2 * g],     pa_h, vl[0], vl[1]);
                mma16816(o[2 * g],     pa_l, vh[0], vh[1]);
                mma16816(o[2 * g + 1], pa_h, vh[2], vh[3]);
                mma16816(o[2 * g + 1], pa_h, vl[2], vl[3]);
                mma16816(o[2 * g + 1], pa_l, vh[2], vh[3]);
            }
        }
        __syncthreads();
    }

    // ---- write O normalized as bf16 hi/lo (proj A operand) ----
    {
        const int rlo = warp * 16 + (lane >> 2);
        const float invlo = 1.0f / l_lo;
        const float invhi = 1.0f / l_hi;
#pragma unroll
        for (int nt = 0; nt < 8; nt++) {
            const int d = h * Dd + nt * 8 + cbase;
            if (rlo < NQ) {
                const long base = ((long)(b * Nn + n0 + rlo)) * Cc + d;
                float a0 = o[nt][0] * invlo, a1 = o[nt][1] * invlo;
                float lx, ly;
                uint32_t hh = pack_hi(a0, a1, lx, ly);
                *(uint32_t*)&g_aoh[base] = hh;
                *(uint32_t*)&g_aol[base] = pack_bf2(lx, ly);
            }
            if (rlo + 8 < NQ) {
                const long base = ((long)(b * Nn + n0 + rlo + 8)) * Cc + d;
                float a0 = o[nt][2] * invhi, a1 = o[nt][3] * invhi;
                float lx, ly;
                uint32_t hh = pack_hi(a0, a1, lx, ly);
                *(uint32_t*)&g_aoh[base] = hh;
                *(uint32_t*)&g_aol[base] = pack_bf2(lx, ly);
            }
        }
    }
}

// ---------------------------------------------------------------------------
extern "C" void kernel_launch(void* const* d_in, const int* in_sizes, int n_in,
                              void* d_out, int out_size)
{
    const float* x      = (const float*)d_in[0];
    const float* aw     = (const float*)d_in[1];
    const float* w_qkv  = (const float*)d_in[2];
    const float* b_qkv  = (const float*)d_in[3];
    const float* w_proj = (const float*)d_in[4];
    const float* b_proj = (const float*)d_in[5];

    float* out   = (float*)d_out;
    float* patch = out + (long)Bb * Nn * Cc;

    // GEMM pipeline needs >48KB dynamic smem: opt in every call.
    cudaFuncSetAttribute(gemm_pipe<0>, cudaFuncAttributeMaxDynamicSharedMemorySize, GEMM_SMEM);
    cudaFuncSetAttribute(gemm_pipe<1>, cudaFuncAttributeMaxDynamicSharedMemorySize, GEMM_SMEM);

    const long nsplit = ((long)NX + NWQ + NWP) / 4;
    split_all<<<(unsigned)((nsplit + 255) / 256), 256>>>(x, w_qkv, w_proj);

    dim3 gq(QKVN / 128, (MM + 127) / 128);     // 18 x 73
    gemm_pipe<0><<<gq, 256, GEMM_SMEM>>>(b_qkv, nullptr);

    dim3 ga(NQT, Bb * Hh);                     // 5 x 192
    attn_mma<<<ga, 256, ATTN_SMEM>>>(aw, patch);

    dim3 gp(Cc / 128, (MM + 127) / 128);       // 6 x 73
    gemm_pipe<1><<<gp, 256, GEMM_SMEM>>>(b_proj, out);
}